// round 5
// baseline (speedup 1.0000x reference)
#include <cuda_runtime.h>
#include <cuda_bf16.h>
#include <math.h>

// Problem constants
#define NUM_EXPERTS 8
#define TOP_K 2
#define HIDDEN 512
#define INTER 2048
#define NTOK 2048            // B*S = 2*1024
#define NSLOT (NTOK * TOP_K) // 4096
#define MAXROWS 2048

#define BM 128
#define BN 128
#define BK 16

// ---------------- device scratch (static, allocation-free) ----------------
__device__ int   g_cnt[NUM_EXPERTS];
__device__ int   g_tok[NUM_EXPERTS][MAXROWS];
__device__ float g_wt[NUM_EXPERTS][MAXROWS];
__device__ float g_probs[NTOK * NUM_EXPERTS];
__device__ float g_hmid[(size_t)NUM_EXPERTS * MAXROWS * INTER]; // 134 MB fp32

// ---------------- helpers ----------------
__device__ __forceinline__ float gelu_tanh(float x) {
    const float c = 0.7978845608028654f; // sqrt(2/pi)
    float x3 = x * x * x;
    return 0.5f * x * (1.0f + tanhf(c * (x + 0.044715f * x3)));
}

// ---------------- kernel 0: reset counters ----------------
__global__ void reset_kernel() {
    int t = threadIdx.x;
    if (t < NUM_EXPERTS) g_cnt[t] = 0;
}

// ---------------- kernel 1: router ----------------
__global__ void router_kernel(const float* __restrict__ hidden,
                              const float* __restrict__ w_router,
                              const float* __restrict__ b_router) {
    __shared__ float wsm[NUM_EXPERTS][HIDDEN];
    int tid = threadIdx.x;
    for (int i = tid; i < NUM_EXPERTS * HIDDEN; i += blockDim.x) {
        int e = i / HIDDEN, h = i % HIDDEN;
        wsm[e][h] = w_router[h * NUM_EXPERTS + e];
    }
    __syncthreads();

    int warp = tid >> 5, lane = tid & 31;
    int t = blockIdx.x * (blockDim.x >> 5) + warp;
    if (t >= NTOK) return;

    const float* x = hidden + (size_t)t * HIDDEN;
    float acc[NUM_EXPERTS];
#pragma unroll
    for (int e = 0; e < NUM_EXPERTS; e++) acc[e] = 0.f;

    for (int i = lane; i < HIDDEN; i += 32) {
        float xv = x[i];
#pragma unroll
        for (int e = 0; e < NUM_EXPERTS; e++) acc[e] += xv * wsm[e][i];
    }
#pragma unroll
    for (int off = 16; off > 0; off >>= 1) {
#pragma unroll
        for (int e = 0; e < NUM_EXPERTS; e++)
            acc[e] += __shfl_xor_sync(0xffffffffu, acc[e], off);
    }

    if (lane == 0) {
        float logits[NUM_EXPERTS];
        float mx = -1e30f;
#pragma unroll
        for (int e = 0; e < NUM_EXPERTS; e++) {
            logits[e] = acc[e] + b_router[e];
            mx = fmaxf(mx, logits[e]);
        }
        float p[NUM_EXPERTS];
        float Z = 0.f;
#pragma unroll
        for (int e = 0; e < NUM_EXPERTS; e++) { p[e] = __expf(logits[e] - mx); Z += p[e]; }
        float invZ = 1.0f / Z;
#pragma unroll
        for (int e = 0; e < NUM_EXPERTS; e++) {
            p[e] *= invZ;
            g_probs[t * NUM_EXPERTS + e] = p[e];
        }
        int i1 = 0; float p1 = p[0];
#pragma unroll
        for (int e = 1; e < NUM_EXPERTS; e++) if (p[e] > p1) { p1 = p[e]; i1 = e; }
        int i2 = -1; float p2 = -1.0f;
#pragma unroll
        for (int e = 0; e < NUM_EXPERTS; e++) {
            if (e != i1 && p[e] > p2) { p2 = p[e]; i2 = e; }
        }
        float rs = 1.0f / (p1 + p2);
        int pos1 = atomicAdd(&g_cnt[i1], 1);
        g_tok[i1][pos1] = t; g_wt[i1][pos1] = p1 * rs;
        int pos2 = atomicAdd(&g_cnt[i2], 1);
        g_tok[i2][pos2] = t; g_wt[i2][pos2] = p2 * rs;
    }
}

// ---------------- kernel 2: balance loss (deterministic reduce) ----------------
__global__ void loss_kernel(float* __restrict__ out, int write_loss) {
    __shared__ float red[256];
    int tid = threadIdx.x;
    float loss_acc = 0.f;
    for (int e = 0; e < NUM_EXPERTS; e++) {
        float s = 0.f;
        for (int t = tid; t < NTOK; t += 256)
            s += g_probs[t * NUM_EXPERTS + e];
        red[tid] = s;
        __syncthreads();
        for (int off = 128; off > 0; off >>= 1) {
            if (tid < off) red[tid] += red[tid + off];
            __syncthreads();
        }
        if (tid == 0) {
            float P = red[0] / (float)NTOK;
            float f = (float)g_cnt[e] / (float)NSLOT;
            loss_acc += f * P;
        }
        __syncthreads();
    }
    if (tid == 0 && write_loss) {
        out[(size_t)NTOK * HIDDEN] = 0.01f * (float)NUM_EXPERTS * loss_acc;
    }
}

// ======================================================================
// GEMM1: 128x128x16 double-buffered, 8x8 micro-tile.
// hmid[e][m][:] = gelu( gather(hidden) @ w1[e] + b1[e] )
// ======================================================================
__global__ void __launch_bounds__(256, 1)
gemm1_kernel(const float* __restrict__ hidden,
             const float* __restrict__ w1,
             const float* __restrict__ b1) {
    int e = blockIdx.z;
    int cnt = g_cnt[e];
    int m0 = blockIdx.y * BM;
    if (m0 >= cnt) return;
    int n0 = blockIdx.x * BN;

    __shared__ float As[2][BK][BM + 4];   // transposed: [k][m]
    __shared__ float Bs[2][BK][BN];
    __shared__ int toks[BM];

    int tid = threadIdx.x;
    if (tid < BM) {
        int m = m0 + tid;
        toks[tid] = (m < cnt) ? g_tok[e][m] : -1;
    }
    __syncthreads();

    const float* w1e = w1 + (size_t)e * HIDDEN * INTER;

    float4 aR[2], bR[2];
    // ---- preload k-block 0 into regs ----
#pragma unroll
    for (int u = 0; u < 2; u++) {
        int idx = tid + u * 256;            // 0..511
        int row = idx >> 2, seg = idx & 3;  // A: 128 rows x 4 float4
        int tok = toks[row];
        aR[u] = (tok >= 0) ? *(const float4*)&hidden[(size_t)tok * HIDDEN + seg * 4]
                           : make_float4(0.f, 0.f, 0.f, 0.f);
        int kr = idx >> 5, c4 = idx & 31;   // B: 16 rows x 32 float4
        bR[u] = *(const float4*)&w1e[(size_t)kr * INTER + n0 + c4 * 4];
    }
#pragma unroll
    for (int u = 0; u < 2; u++) {
        int idx = tid + u * 256;
        int row = idx >> 2, seg = idx & 3;
        As[0][seg * 4 + 0][row] = aR[u].x;
        As[0][seg * 4 + 1][row] = aR[u].y;
        As[0][seg * 4 + 2][row] = aR[u].z;
        As[0][seg * 4 + 3][row] = aR[u].w;
        int kr = idx >> 5, c4 = idx & 31;
        *(float4*)&Bs[0][kr][c4 * 4] = bR[u];
    }
    __syncthreads();

    int tx = tid & 15, ty = tid >> 4;       // 16x16 thread grid, 8x8 each
    float acc[8][8];
#pragma unroll
    for (int i = 0; i < 8; i++)
#pragma unroll
        for (int j = 0; j < 8; j++) acc[i][j] = 0.f;

    int cur = 0;
    const int KT = HIDDEN / BK;             // 32
    for (int kt = 0; kt < KT; kt++) {
        if (kt + 1 < KT) {
            int k0 = (kt + 1) * BK;
#pragma unroll
            for (int u = 0; u < 2; u++) {
                int idx = tid + u * 256;
                int row = idx >> 2, seg = idx & 3;
                int tok = toks[row];
                aR[u] = (tok >= 0) ? *(const float4*)&hidden[(size_t)tok * HIDDEN + k0 + seg * 4]
                                   : make_float4(0.f, 0.f, 0.f, 0.f);
                int kr = idx >> 5, c4 = idx & 31;
                bR[u] = *(const float4*)&w1e[(size_t)(k0 + kr) * INTER + n0 + c4 * 4];
            }
        }
#pragma unroll
        for (int kk = 0; kk < BK; kk++) {
            float4 a0 = *(const float4*)&As[cur][kk][ty * 8];
            float4 a1 = *(const float4*)&As[cur][kk][ty * 8 + 4];
            float4 b0 = *(const float4*)&Bs[cur][kk][tx * 8];
            float4 b1f = *(const float4*)&Bs[cur][kk][tx * 8 + 4];
            float av[8] = {a0.x, a0.y, a0.z, a0.w, a1.x, a1.y, a1.z, a1.w};
            float bv[8] = {b0.x, b0.y, b0.z, b0.w, b1f.x, b1f.y, b1f.z, b1f.w};
#pragma unroll
            for (int i = 0; i < 8; i++)
#pragma unroll
                for (int j = 0; j < 8; j++)
                    acc[i][j] += av[i] * bv[j];
        }
        if (kt + 1 < KT) {
            int nxt = cur ^ 1;
#pragma unroll
            for (int u = 0; u < 2; u++) {
                int idx = tid + u * 256;
                int row = idx >> 2, seg = idx & 3;
                As[nxt][seg * 4 + 0][row] = aR[u].x;
                As[nxt][seg * 4 + 1][row] = aR[u].y;
                As[nxt][seg * 4 + 2][row] = aR[u].z;
                As[nxt][seg * 4 + 3][row] = aR[u].w;
                int kr = idx >> 5, c4 = idx & 31;
                *(float4*)&Bs[nxt][kr][c4 * 4] = bR[u];
            }
            __syncthreads();
            cur = nxt;
        }
    }

    // epilogue: bias + gelu, write hmid
    float4 bb0 = *(const float4*)&b1[(size_t)e * INTER + n0 + tx * 8];
    float4 bb1 = *(const float4*)&b1[(size_t)e * INTER + n0 + tx * 8 + 4];
    float bias[8] = {bb0.x, bb0.y, bb0.z, bb0.w, bb1.x, bb1.y, bb1.z, bb1.w};
#pragma unroll
    for (int i = 0; i < 8; i++) {
        int m = m0 + ty * 8 + i;
        if (m < cnt) {
            float v[8];
#pragma unroll
            for (int j = 0; j < 8; j++) v[j] = gelu_tanh(acc[i][j] + bias[j]);
            float* dst = &g_hmid[((size_t)e * MAXROWS + m) * INTER + n0 + tx * 8];
            *(float4*)&dst[0] = make_float4(v[0], v[1], v[2], v[3]);
            *(float4*)&dst[4] = make_float4(v[4], v[5], v[6], v[7]);
        }
    }
}

// ======================================================================
// GEMM2: 128x128x16 double-buffered, 8x8 micro-tile.
// out[tok] += wt * ( hmid[e] @ w2[e] + b2[e] )
// ======================================================================
__global__ void __launch_bounds__(256, 1)
gemm2_kernel(const float* __restrict__ w2,
             const float* __restrict__ b2,
             float* __restrict__ out) {
    int e = blockIdx.z;
    int cnt = g_cnt[e];
    int m0 = blockIdx.y * BM;
    if (m0 >= cnt) return;
    int n0 = blockIdx.x * BN;

    __shared__ float As[2][BK][BM + 4];
    __shared__ float Bs[2][BK][BN];

    int tid = threadIdx.x;
    const float* w2e = w2 + (size_t)e * INTER * HIDDEN;
    const float* ae  = &g_hmid[(size_t)e * MAXROWS * INTER];

    float4 aR[2], bR[2];
#pragma unroll
    for (int u = 0; u < 2; u++) {
        int idx = tid + u * 256;
        int row = idx >> 2, seg = idx & 3;
        int gm = m0 + row;
        aR[u] = (gm < cnt) ? *(const float4*)&ae[(size_t)gm * INTER + seg * 4]
                           : make_float4(0.f, 0.f, 0.f, 0.f);
        int kr = idx >> 5, c4 = idx & 31;
        bR[u] = *(const float4*)&w2e[(size_t)kr * HIDDEN + n0 + c4 * 4];
    }
#pragma unroll
    for (int u = 0; u < 2; u++) {
        int idx = tid + u * 256;
        int row = idx >> 2, seg = idx & 3;
        As[0][seg * 4 + 0][row] = aR[u].x;
        As[0][seg * 4 + 1][row] = aR[u].y;
        As[0][seg * 4 + 2][row] = aR[u].z;
        As[0][seg * 4 + 3][row] = aR[u].w;
        int kr = idx >> 5, c4 = idx & 31;
        *(float4*)&Bs[0][kr][c4 * 4] = bR[u];
    }
    __syncthreads();

    int tx = tid & 15, ty = tid >> 4;
    float acc[8][8];
#pragma unroll
    for (int i = 0; i < 8; i++)
#pragma unroll
        for (int j = 0; j < 8; j++) acc[i][j] = 0.f;

    int cur = 0;
    const int KT = INTER / BK;  // 128
    for (int kt = 0; kt < KT; kt++) {
        if (kt + 1 < KT) {
            int k0 = (kt + 1) * BK;
#pragma unroll
            for (int u = 0; u < 2; u++) {
                int idx = tid + u * 256;
                int row = idx >> 2, seg = idx & 3;
                int gm = m0 + row;
                aR[u] = (gm < cnt) ? *(const float4*)&ae[(size_t)gm * INTER + k0 + seg * 4]
                                   : make_float4(0.f, 0.f, 0.f, 0.f);
                int kr = idx >> 5, c4 = idx & 31;
                bR[u] = *(const float4*)&w2e[(size_t)(k0 + kr) * HIDDEN + n0 + c4 * 4];
            }
        }
#pragma unroll
        for (int kk = 0; kk < BK; kk++) {
            float4 a0 = *(const float4*)&As[cur][kk][ty * 8];
            float4 a1 = *(const float4*)&As[cur][kk][ty * 8 + 4];
            float4 b0 = *(const float4*)&Bs[cur][kk][tx * 8];
            float4 b1f = *(const float4*)&Bs[cur][kk][tx * 8 + 4];
            float av[8] = {a0.x, a0.y, a0.z, a0.w, a1.x, a1.y, a1.z, a1.w};
            float bv[8] = {b0.x, b0.y, b0.z, b0.w, b1f.x, b1f.y, b1f.z, b1f.w};
#pragma unroll
            for (int i = 0; i < 8; i++)
#pragma unroll
                for (int j = 0; j < 8; j++)
                    acc[i][j] += av[i] * bv[j];
        }
        if (kt + 1 < KT) {
            int nxt = cur ^ 1;
#pragma unroll
            for (int u = 0; u < 2; u++) {
                int idx = tid + u * 256;
                int row = idx >> 2, seg = idx & 3;
                As[nxt][seg * 4 + 0][row] = aR[u].x;
                As[nxt][seg * 4 + 1][row] = aR[u].y;
                As[nxt][seg * 4 + 2][row] = aR[u].z;
                As[nxt][seg * 4 + 3][row] = aR[u].w;
                int kr = idx >> 5, c4 = idx & 31;
                *(float4*)&Bs[nxt][kr][c4 * 4] = bR[u];
            }
            __syncthreads();
            cur = nxt;
        }
    }

    // epilogue: weighted atomic accumulate onto residual-initialized out
    float4 bb0 = *(const float4*)&b2[(size_t)e * HIDDEN + n0 + tx * 8];
    float4 bb1 = *(const float4*)&b2[(size_t)e * HIDDEN + n0 + tx * 8 + 4];
    float bias[8] = {bb0.x, bb0.y, bb0.z, bb0.w, bb1.x, bb1.y, bb1.z, bb1.w};
#pragma unroll
    for (int i = 0; i < 8; i++) {
        int m = m0 + ty * 8 + i;
        if (m < cnt) {
            float w = g_wt[e][m];
            int tok = g_tok[e][m];
            float* op = out + (size_t)tok * HIDDEN + n0 + tx * 8;
#pragma unroll
            for (int j = 0; j < 8; j++)
                atomicAdd(op + j, (acc[i][j] + bias[j]) * w);
        }
    }
}

// ---------------- launch ----------------
extern "C" void kernel_launch(void* const* d_in, const int* in_sizes, int n_in,
                              void* d_out, int out_size) {
    const float* hidden   = (const float*)d_in[0]; // (2,1024,512)
    const float* w_router = (const float*)d_in[1]; // (512,8)
    const float* b_router = (const float*)d_in[2]; // (8,)
    const float* w1       = (const float*)d_in[3]; // (8,512,2048)
    const float* b1       = (const float*)d_in[4]; // (8,2048)
    const float* w2       = (const float*)d_in[5]; // (8,2048,512)
    const float* b2       = (const float*)d_in[6]; // (8,512)
    float* out = (float*)d_out;

    // residual init: out[:NTOK*H] = hidden
    cudaMemcpyAsync(out, hidden, (size_t)NTOK * HIDDEN * sizeof(float),
                    cudaMemcpyDeviceToDevice);

    reset_kernel<<<1, 32>>>();
    router_kernel<<<NTOK / 8, 256>>>(hidden, w_router, b_router);

    int write_loss = (out_size > NTOK * HIDDEN) ? 1 : 0;
    loss_kernel<<<1, 256>>>(out, write_loss);

    // GEMM1: N tiles = 2048/128 = 16, M tiles = 16, 8 experts
    gemm1_kernel<<<dim3(INTER / BN, MAXROWS / BM, NUM_EXPERTS), 256>>>(hidden, w1, b1);
    // GEMM2: N tiles = 512/128 = 4
    gemm2_kernel<<<dim3(HIDDEN / BN, MAXROWS / BM, NUM_EXPERTS), 256>>>(w2, b2, out);
}

// round 8
// speedup vs baseline: 3.1754x; 3.1754x over previous
#include <cuda_runtime.h>
#include <cuda_bf16.h>
#include <math.h>

// Problem constants
#define NUM_EXPERTS 8
#define TOP_K 2
#define HIDDEN 512
#define INTER 2048
#define NTOK 2048
#define NSLOT (NTOK * TOP_K)
#define MAXROWS 2048

#define BKC 64            // k elements per smem chunk (128 B per row in bf16)
#define ATILE_BYTES 16384 // 128 rows * 64 bf16 * 2B

// ---------------- device scratch (static, allocation-free) ----------------
__device__ int   g_cnt[NUM_EXPERTS];
__device__ int   g_tok[NUM_EXPERTS][MAXROWS];
__device__ float g_wt[NUM_EXPERTS][MAXROWS];
__device__ float g_probs[NTOK * NUM_EXPERTS];
// packed (hi | lo<<16) bf16 pair per element
__device__ unsigned int g_hmid[(size_t)NUM_EXPERTS * MAXROWS * INTER];
// transposed, split weights: [E][N][K] K-major bf16
__device__ __nv_bfloat16 g_w1t_hi[(size_t)NUM_EXPERTS * INTER * HIDDEN];
__device__ __nv_bfloat16 g_w1t_lo[(size_t)NUM_EXPERTS * INTER * HIDDEN];
__device__ __nv_bfloat16 g_w2t_hi[(size_t)NUM_EXPERTS * HIDDEN * INTER];
__device__ __nv_bfloat16 g_w2t_lo[(size_t)NUM_EXPERTS * HIDDEN * INTER];

// ---------------- helpers ----------------
__device__ __forceinline__ unsigned smem_u32(const void* p) {
    unsigned a;
    asm("{ .reg .u64 t; cvta.to.shared.u64 t, %1; cvt.u32.u64 %0, t; }"
        : "=r"(a) : "l"(p));
    return a;
}
__device__ __forceinline__ unsigned sw128(unsigned off) {
    return off ^ ((off >> 3) & 0x70);
}
__device__ __forceinline__ unsigned pack_split(float v) {
    __nv_bfloat16 h = __float2bfloat16(v);
    __nv_bfloat16 l = __float2bfloat16(v - __bfloat162float(h));
    return (unsigned)__bfloat16_as_ushort(h) | ((unsigned)__bfloat16_as_ushort(l) << 16);
}
__device__ __forceinline__ unsigned pack2_hi(float a, float b,
                                             __nv_bfloat16& ha, __nv_bfloat16& hb) {
    ha = __float2bfloat16(a);
    hb = __float2bfloat16(b);
    return (unsigned)__bfloat16_as_ushort(ha) | ((unsigned)__bfloat16_as_ushort(hb) << 16);
}
__device__ __forceinline__ float gelu_tanh(float x) {
    const float c = 0.7978845608028654f;
    float x3 = x * x * x;
    return 0.5f * x * (1.0f + tanhf(c * (x + 0.044715f * x3)));
}

#define LDSM4(r, addr) \
    asm volatile("ldmatrix.sync.aligned.m8n8.x4.shared.b16 {%0,%1,%2,%3}, [%4];" \
        : "=r"((r)[0]), "=r"((r)[1]), "=r"((r)[2]), "=r"((r)[3]) : "r"(addr))

#define MMA16816(c, a, b0v, b1v) \
    asm volatile("mma.sync.aligned.m16n8k16.row.col.f32.bf16.bf16.f32 " \
        "{%0,%1,%2,%3}, {%4,%5,%6,%7}, {%8,%9}, {%0,%1,%2,%3};" \
        : "+f"((c)[0]), "+f"((c)[1]), "+f"((c)[2]), "+f"((c)[3]) \
        : "r"((a)[0]), "r"((a)[1]), "r"((a)[2]), "r"((a)[3]), "r"(b0v), "r"(b1v))

// ---------------- kernel 0: reset counters ----------------
__global__ void reset_kernel() {
    int t = threadIdx.x;
    if (t < NUM_EXPERTS) g_cnt[t] = 0;
}

// ---------------- kernel 1: router ----------------
__global__ void router_kernel(const float* __restrict__ hidden,
                              const float* __restrict__ w_router,
                              const float* __restrict__ b_router) {
    __shared__ float wsm[NUM_EXPERTS][HIDDEN];
    int tid = threadIdx.x;
    for (int i = tid; i < NUM_EXPERTS * HIDDEN; i += blockDim.x) {
        int e = i / HIDDEN, h = i % HIDDEN;
        wsm[e][h] = w_router[h * NUM_EXPERTS + e];
    }
    __syncthreads();

    int warp = tid >> 5, lane = tid & 31;
    int t = blockIdx.x * (blockDim.x >> 5) + warp;
    if (t >= NTOK) return;

    const float* x = hidden + (size_t)t * HIDDEN;
    float acc[NUM_EXPERTS];
#pragma unroll
    for (int e = 0; e < NUM_EXPERTS; e++) acc[e] = 0.f;
    for (int i = lane; i < HIDDEN; i += 32) {
        float xv = x[i];
#pragma unroll
        for (int e = 0; e < NUM_EXPERTS; e++) acc[e] += xv * wsm[e][i];
    }
#pragma unroll
    for (int off = 16; off > 0; off >>= 1) {
#pragma unroll
        for (int e = 0; e < NUM_EXPERTS; e++)
            acc[e] += __shfl_xor_sync(0xffffffffu, acc[e], off);
    }
    if (lane == 0) {
        float logits[NUM_EXPERTS], mx = -1e30f;
#pragma unroll
        for (int e = 0; e < NUM_EXPERTS; e++) {
            logits[e] = acc[e] + b_router[e];
            mx = fmaxf(mx, logits[e]);
        }
        float p[NUM_EXPERTS], Z = 0.f;
#pragma unroll
        for (int e = 0; e < NUM_EXPERTS; e++) { p[e] = __expf(logits[e] - mx); Z += p[e]; }
        float invZ = 1.0f / Z;
#pragma unroll
        for (int e = 0; e < NUM_EXPERTS; e++) {
            p[e] *= invZ;
            g_probs[t * NUM_EXPERTS + e] = p[e];
        }
        int i1 = 0; float p1 = p[0];
#pragma unroll
        for (int e = 1; e < NUM_EXPERTS; e++) if (p[e] > p1) { p1 = p[e]; i1 = e; }
        int i2 = -1; float p2 = -1.0f;
#pragma unroll
        for (int e = 0; e < NUM_EXPERTS; e++)
            if (e != i1 && p[e] > p2) { p2 = p[e]; i2 = e; }
        float rs = 1.0f / (p1 + p2);
        int pos1 = atomicAdd(&g_cnt[i1], 1);
        g_tok[i1][pos1] = t; g_wt[i1][pos1] = p1 * rs;
        int pos2 = atomicAdd(&g_cnt[i2], 1);
        g_tok[i2][pos2] = t; g_wt[i2][pos2] = p2 * rs;
    }
}

// ---------------- kernel 2: balance loss ----------------
__global__ void loss_kernel(float* __restrict__ out, int write_loss) {
    __shared__ float red[256];
    int tid = threadIdx.x;
    float loss_acc = 0.f;
    for (int e = 0; e < NUM_EXPERTS; e++) {
        float s = 0.f;
        for (int t = tid; t < NTOK; t += 256)
            s += g_probs[t * NUM_EXPERTS + e];
        red[tid] = s;
        __syncthreads();
        for (int off = 128; off > 0; off >>= 1) {
            if (tid < off) red[tid] += red[tid + off];
            __syncthreads();
        }
        if (tid == 0) {
            float P = red[0] / (float)NTOK;
            float f = (float)g_cnt[e] / (float)NSLOT;
            loss_acc += f * P;
        }
        __syncthreads();
    }
    if (tid == 0 && write_loss)
        out[(size_t)NTOK * HIDDEN] = 0.01f * (float)NUM_EXPERTS * loss_acc;
}

// ---------------- kernel 3: transpose + bf16 split weights ----------------
// w: [E][K][N] fp32  ->  hi/lo: [E][N][K] bf16   (which: 0 -> w1, 1 -> w2)
__global__ void transpose_split_kernel(const float* __restrict__ w,
                                       int which, int K, int N) {
    __nv_bfloat16* hi = which ? g_w2t_hi : g_w1t_hi;
    __nv_bfloat16* lo = which ? g_w2t_lo : g_w1t_lo;
    __shared__ float tile[32][33];
    int e = blockIdx.z;
    int n0 = blockIdx.x * 32, k0 = blockIdx.y * 32;
    const float* we = w + (size_t)e * K * N;
    int tx = threadIdx.x, ty = threadIdx.y; // 32 x 8
#pragma unroll
    for (int r = 0; r < 4; r++) {
        int k = k0 + ty + r * 8;
        tile[ty + r * 8][tx] = we[(size_t)k * N + n0 + tx];
    }
    __syncthreads();
#pragma unroll
    for (int r = 0; r < 4; r++) {
        int n = n0 + ty + r * 8;
        float v = tile[tx][ty + r * 8];
        __nv_bfloat16 h = __float2bfloat16(v);
        __nv_bfloat16 l = __float2bfloat16(v - __bfloat162float(h));
        size_t o = ((size_t)e * N + n) * K + k0 + tx;
        hi[o] = h; lo[o] = l;
    }
}

// ======================================================================
// GEMM1 (mma.sync bf16, 3-way split): hmid = gelu(gather(hidden) @ w1 + b1)
// CTA 128x128, K chunks of 64; 8 warps (2m x 4n), warp tile 64x32.
// ======================================================================
__global__ void __launch_bounds__(256, 2)
gemm1_mma(const float* __restrict__ hidden, const float* __restrict__ b1) {
    int e = blockIdx.z;
    int cnt = g_cnt[e];
    int m0 = blockIdx.y * 128;
    if (m0 >= cnt) return;
    int n0 = blockIdx.x * 128;

    extern __shared__ char dsm[];
    unsigned sb = smem_u32(dsm);
    unsigned base = (sb + 1023u) & ~1023u;
    char* mem = dsm + (base - sb);
    char* Ah = mem;
    char* Al = mem + ATILE_BYTES;
    char* Bh = mem + 2 * ATILE_BYTES;
    char* Bl = mem + 3 * ATILE_BYTES;
    unsigned uAh = base, uAl = base + ATILE_BYTES;
    unsigned uBh = base + 2 * ATILE_BYTES, uBl = base + 3 * ATILE_BYTES;

    __shared__ int toks[128];
    int tid = threadIdx.x, wid = tid >> 5, lane = tid & 31;
    if (tid < 128) toks[tid] = (m0 + tid < cnt) ? g_tok[e][m0 + tid] : -1;
    __syncthreads();

    int wm = wid >> 2, wn = wid & 3;
    // ldmatrix lane geometry
    int rA = (lane & 7) + 8 * ((lane >> 3) & 1);
    int cA = lane >> 4;
    int rB = (lane & 7) + 8 * (lane >> 4);
    int cB = (lane >> 3) & 1;

    const __nv_bfloat16* w1h = g_w1t_hi + (size_t)e * INTER * HIDDEN;
    const __nv_bfloat16* w1l = g_w1t_lo + (size_t)e * INTER * HIDDEN;

    float acc[4][4][4];
#pragma unroll
    for (int i = 0; i < 4; i++)
#pragma unroll
        for (int j = 0; j < 4; j++)
#pragma unroll
            for (int q = 0; q < 4; q++) acc[i][j][q] = 0.f;

    const int KT = HIDDEN / BKC; // 8
    for (int kt = 0; kt < KT; kt++) {
        int k0 = kt * BKC;
        // ---- A: gather 128 rows x 64 k fp32, split bf16 hi/lo ----
#pragma unroll
        for (int u = 0; u < 8; u++) {
            int idx = tid + u * 256;
            int row = idx >> 4, seg = idx & 15;
            int tok = toks[row];
            float4 v = (tok >= 0)
                ? *(const float4*)&hidden[(size_t)tok * HIDDEN + k0 + seg * 4]
                : make_float4(0.f, 0.f, 0.f, 0.f);
            __nv_bfloat16 h0, h1, h2, h3, d0, d1, d2, d3;
            unsigned h01 = pack2_hi(v.x, v.y, h0, h1);
            unsigned h23 = pack2_hi(v.z, v.w, h2, h3);
            unsigned l01 = pack2_hi(v.x - __bfloat162float(h0), v.y - __bfloat162float(h1), d0, d1);
            unsigned l23 = pack2_hi(v.z - __bfloat162float(h2), v.w - __bfloat162float(h3), d2, d3);
            unsigned so = sw128((unsigned)(row * 128 + seg * 8));
            *(uint2*)(Ah + so) = make_uint2(h01, h23);
            *(uint2*)(Al + so) = make_uint2(l01, l23);
        }
        // ---- B: 128 n-rows x 64 k bf16 hi/lo ----
#pragma unroll
        for (int u = 0; u < 4; u++) {
            int idx = tid + u * 256;
            int row = idx >> 3, seg = idx & 7;
            size_t src = (size_t)(n0 + row) * HIDDEN + k0 + seg * 8;
            unsigned so = sw128((unsigned)(row * 128 + seg * 16));
            *(uint4*)(Bh + so) = *(const uint4*)(w1h + src);
            *(uint4*)(Bl + so) = *(const uint4*)(w1l + src);
        }
        __syncthreads();
#pragma unroll
        for (int k16 = 0; k16 < 4; k16++) {
            unsigned Afh[4][4], Afl[4][4], Bf[2][4];
#pragma unroll
            for (int mt = 0; mt < 4; mt++) {
                unsigned off = sw128((unsigned)((64 * wm + 16 * mt + rA) * 128 + (2 * k16 + cA) * 16));
                LDSM4(Afh[mt], uAh + off);
                LDSM4(Afl[mt], uAl + off);
            }
#pragma unroll
            for (int pr = 0; pr < 2; pr++) {
                unsigned off = sw128((unsigned)((32 * wn + 16 * pr + rB) * 128 + (2 * k16 + cB) * 16));
                LDSM4(Bf[pr], uBh + off);
            }
            // Ah*Bh + Al*Bh
#pragma unroll
            for (int mt = 0; mt < 4; mt++)
#pragma unroll
                for (int nt = 0; nt < 4; nt++) {
                    unsigned b0 = Bf[nt >> 1][(nt & 1) * 2], b1v = Bf[nt >> 1][(nt & 1) * 2 + 1];
                    MMA16816(acc[mt][nt], Afh[mt], b0, b1v);
                }
#pragma unroll
            for (int mt = 0; mt < 4; mt++)
#pragma unroll
                for (int nt = 0; nt < 4; nt++) {
                    unsigned b0 = Bf[nt >> 1][(nt & 1) * 2], b1v = Bf[nt >> 1][(nt & 1) * 2 + 1];
                    MMA16816(acc[mt][nt], Afl[mt], b0, b1v);
                }
            // Ah*Bl
#pragma unroll
            for (int pr = 0; pr < 2; pr++) {
                unsigned off = sw128((unsigned)((32 * wn + 16 * pr + rB) * 128 + (2 * k16 + cB) * 16));
                LDSM4(Bf[pr], uBl + off);
            }
#pragma unroll
            for (int mt = 0; mt < 4; mt++)
#pragma unroll
                for (int nt = 0; nt < 4; nt++) {
                    unsigned b0 = Bf[nt >> 1][(nt & 1) * 2], b1v = Bf[nt >> 1][(nt & 1) * 2 + 1];
                    MMA16816(acc[mt][nt], Afh[mt], b0, b1v);
                }
        }
        __syncthreads();
    }

    // ---- epilogue: bias + gelu, pack hi/lo, write hmid ----
    int g = lane >> 2, tg = lane & 3;
#pragma unroll
    for (int mt = 0; mt < 4; mt++) {
        int mA = m0 + 64 * wm + 16 * mt + g;
        int mB = mA + 8;
#pragma unroll
        for (int nt = 0; nt < 4; nt++) {
            int n = n0 + 32 * wn + 8 * nt + 2 * tg;
            float2 bb = *(const float2*)&b1[(size_t)e * INTER + n];
            if (mA < cnt) {
                float v0 = gelu_tanh(acc[mt][nt][0] + bb.x);
                float v1 = gelu_tanh(acc[mt][nt][1] + bb.y);
                *(uint2*)&g_hmid[((size_t)e * MAXROWS + mA) * INTER + n] =
                    make_uint2(pack_split(v0), pack_split(v1));
            }
            if (mB < cnt) {
                float v2 = gelu_tanh(acc[mt][nt][2] + bb.x);
                float v3 = gelu_tanh(acc[mt][nt][3] + bb.y);
                *(uint2*)&g_hmid[((size_t)e * MAXROWS + mB) * INTER + n] =
                    make_uint2(pack_split(v2), pack_split(v3));
            }
        }
    }
}

// ======================================================================
// GEMM2 (mma.sync bf16, 3-way split): out[tok] += wt*(hmid @ w2 + b2)
// CTA 128x64, K chunks of 64; 8 warps (2m x 4n), warp tile 64x16.
// ======================================================================
__global__ void __launch_bounds__(256, 2)
gemm2_mma(const float* __restrict__ b2, float* __restrict__ out) {
    int e = blockIdx.z;
    int cnt = g_cnt[e];
    int m0 = blockIdx.y * 128;
    if (m0 >= cnt) return;
    int n0 = blockIdx.x * 64;

    extern __shared__ char dsm[];
    unsigned sb = smem_u32(dsm);
    unsigned base = (sb + 1023u) & ~1023u;
    char* mem = dsm + (base - sb);
    char* Ah = mem;
    char* Al = mem + ATILE_BYTES;
    char* Bh = mem + 2 * ATILE_BYTES;                 // 64 rows -> 8 KB
    char* Bl = mem + 2 * ATILE_BYTES + ATILE_BYTES / 2;
    unsigned uAh = base, uAl = base + ATILE_BYTES;
    unsigned uBh = base + 2 * ATILE_BYTES, uBl = base + 2 * ATILE_BYTES + ATILE_BYTES / 2;

    int tid = threadIdx.x, wid = tid >> 5, lane = tid & 31;
    int wm = wid >> 2, wn = wid & 3;
    int rA = (lane & 7) + 8 * ((lane >> 3) & 1);
    int cA = lane >> 4;
    int rB = (lane & 7) + 8 * (lane >> 4);
    int cB = (lane >> 3) & 1;

    const __nv_bfloat16* w2h = g_w2t_hi + (size_t)e * HIDDEN * INTER;
    const __nv_bfloat16* w2l = g_w2t_lo + (size_t)e * HIDDEN * INTER;
    const unsigned* ae = g_hmid + (size_t)e * MAXROWS * INTER;

    float acc[4][2][4];
#pragma unroll
    for (int i = 0; i < 4; i++)
#pragma unroll
        for (int j = 0; j < 2; j++)
#pragma unroll
            for (int q = 0; q < 4; q++) acc[i][j][q] = 0.f;

    const int KT = INTER / BKC; // 32
    for (int kt = 0; kt < KT; kt++) {
        int k0 = kt * BKC;
        // ---- A: hmid packed hi/lo, 128 rows x 64 k ----
#pragma unroll
        for (int u = 0; u < 8; u++) {
            int idx = tid + u * 256;
            int row = idx >> 4, seg = idx & 15;
            int gm = m0 + row;
            uint4 v = (gm < cnt)
                ? *(const uint4*)&ae[(size_t)gm * INTER + k0 + seg * 4]
                : make_uint4(0u, 0u, 0u, 0u);
            unsigned h01 = (v.x & 0xFFFFu) | ((v.y & 0xFFFFu) << 16);
            unsigned h23 = (v.z & 0xFFFFu) | ((v.w & 0xFFFFu) << 16);
            unsigned l01 = (v.x >> 16) | (v.y & 0xFFFF0000u);
            unsigned l23 = (v.z >> 16) | (v.w & 0xFFFF0000u);
            unsigned so = sw128((unsigned)(row * 128 + seg * 8));
            *(uint2*)(Ah + so) = make_uint2(h01, h23);
            *(uint2*)(Al + so) = make_uint2(l01, l23);
        }
        // ---- B: 64 n-rows x 64 k hi/lo ----
#pragma unroll
        for (int u = 0; u < 2; u++) {
            int idx = tid + u * 256;
            int row = idx >> 3, seg = idx & 7;
            size_t src = (size_t)(n0 + row) * INTER + k0 + seg * 8;
            unsigned so = sw128((unsigned)(row * 128 + seg * 16));
            *(uint4*)(Bh + so) = *(const uint4*)(w2h + src);
            *(uint4*)(Bl + so) = *(const uint4*)(w2l + src);
        }
        __syncthreads();
#pragma unroll
        for (int k16 = 0; k16 < 4; k16++) {
            unsigned Afh[4][4], Afl[4][4], Bf[4];
#pragma unroll
            for (int mt = 0; mt < 4; mt++) {
                unsigned off = sw128((unsigned)((64 * wm + 16 * mt + rA) * 128 + (2 * k16 + cA) * 16));
                LDSM4(Afh[mt], uAh + off);
                LDSM4(Afl[mt], uAl + off);
            }
            {
                unsigned off = sw128((unsigned)((16 * wn + rB) * 128 + (2 * k16 + cB) * 16));
                LDSM4(Bf, uBh + off);
            }
#pragma unroll
            for (int mt = 0; mt < 4; mt++)
#pragma unroll
                for (int nt = 0; nt < 2; nt++)
                    MMA16816(acc[mt][nt], Afh[mt], Bf[nt * 2], Bf[nt * 2 + 1]);
#pragma unroll
            for (int mt = 0; mt < 4; mt++)
#pragma unroll
                for (int nt = 0; nt < 2; nt++)
                    MMA16816(acc[mt][nt], Afl[mt], Bf[nt * 2], Bf[nt * 2 + 1]);
            {
                unsigned off = sw128((unsigned)((16 * wn + rB) * 128 + (2 * k16 + cB) * 16));
                LDSM4(Bf, uBl + off);
            }
#pragma unroll
            for (int mt = 0; mt < 4; mt++)
#pragma unroll
                for (int nt = 0; nt < 2; nt++)
                    MMA16816(acc[mt][nt], Afh[mt], Bf[nt * 2], Bf[nt * 2 + 1]);
        }
        __syncthreads();
    }

    // ---- epilogue: weighted atomic accumulate onto residual out ----
    int g = lane >> 2, tg = lane & 3;
#pragma unroll
    for (int mt = 0; mt < 4; mt++) {
        int mA = m0 + 64 * wm + 16 * mt + g;
        int mB = mA + 8;
        float wA = (mA < cnt) ? g_wt[e][mA] : 0.f;
        float wB = (mB < cnt) ? g_wt[e][mB] : 0.f;
        int tokA = (mA < cnt) ? g_tok[e][mA] : 0;
        int tokB = (mB < cnt) ? g_tok[e][mB] : 0;
#pragma unroll
        for (int nt = 0; nt < 2; nt++) {
            int n = n0 + 16 * wn + 8 * nt + 2 * tg;
            float2 bb = *(const float2*)&b2[(size_t)e * HIDDEN + n];
            if (mA < cnt) {
                float* op = out + (size_t)tokA * HIDDEN + n;
                atomicAdd(op,     (acc[mt][nt][0] + bb.x) * wA);
                atomicAdd(op + 1, (acc[mt][nt][1] + bb.y) * wA);
            }
            if (mB < cnt) {
                float* op = out + (size_t)tokB * HIDDEN + n;
                atomicAdd(op,     (acc[mt][nt][2] + bb.x) * wB);
                atomicAdd(op + 1, (acc[mt][nt][3] + bb.y) * wB);
            }
        }
    }
}

// ---------------- launch ----------------
extern "C" void kernel_launch(void* const* d_in, const int* in_sizes, int n_in,
                              void* d_out, int out_size) {
    const float* hidden   = (const float*)d_in[0];
    const float* w_router = (const float*)d_in[1];
    const float* b_router = (const float*)d_in[2];
    const float* w1       = (const float*)d_in[3];
    const float* b1       = (const float*)d_in[4];
    const float* w2       = (const float*)d_in[5];
    const float* b2       = (const float*)d_in[6];
    float* out = (float*)d_out;

    const int SMEM1 = 4 * ATILE_BYTES + 1024;                    // 66560
    const int SMEM2 = 3 * ATILE_BYTES + 1024;                    // 50176
    cudaFuncSetAttribute(gemm1_mma, cudaFuncAttributeMaxDynamicSharedMemorySize, SMEM1);
    cudaFuncSetAttribute(gemm2_mma, cudaFuncAttributeMaxDynamicSharedMemorySize, SMEM2);

    // residual init
    cudaMemcpyAsync(out, hidden, (size_t)NTOK * HIDDEN * sizeof(float),
                    cudaMemcpyDeviceToDevice);

    reset_kernel<<<1, 32>>>();
    router_kernel<<<NTOK / 8, 256>>>(hidden, w_router, b_router);

    int write_loss = (out_size > NTOK * HIDDEN) ? 1 : 0;
    loss_kernel<<<1, 256>>>(out, write_loss);

    transpose_split_kernel<<<dim3(INTER / 32, HIDDEN / 32, NUM_EXPERTS), dim3(32, 8)>>>(
        w1, 0, HIDDEN, INTER);
    transpose_split_kernel<<<dim3(HIDDEN / 32, INTER / 32, NUM_EXPERTS), dim3(32, 8)>>>(
        w2, 1, INTER, HIDDEN);

    gemm1_mma<<<dim3(INTER / 128, MAXROWS / 128, NUM_EXPERTS), 256, SMEM1>>>(hidden, b1);
    gemm2_mma<<<dim3(HIDDEN / 64, MAXROWS / 128, NUM_EXPERTS), 256, SMEM2>>>(b2, out);
}

// round 9
// speedup vs baseline: 3.8996x; 1.2281x over previous
#include <cuda_runtime.h>
#include <cuda_bf16.h>
#include <math.h>

// Problem constants
#define NUM_EXPERTS 8
#define TOP_K 2
#define HIDDEN 512
#define INTER 2048
#define NTOK 2048
#define NSLOT (NTOK * TOP_K)
#define MAXROWS 2048

#define BKC 64            // k per chunk (128 B bf16 rows)

// ---------------- device scratch ----------------
__device__ int   g_cnt[NUM_EXPERTS];
__device__ int   g_tok[NUM_EXPERTS][MAXROWS];
__device__ float g_wt[NUM_EXPERTS][MAXROWS];
__device__ float g_probs[NTOK * NUM_EXPERTS];
// split activation planes
__device__ __nv_bfloat16 g_xh[(size_t)NTOK * HIDDEN];
__device__ __nv_bfloat16 g_xl[(size_t)NTOK * HIDDEN];
// hmid hi/lo planes
__device__ __nv_bfloat16 g_hmid_hi[(size_t)NUM_EXPERTS * MAXROWS * INTER];
__device__ __nv_bfloat16 g_hmid_lo[(size_t)NUM_EXPERTS * MAXROWS * INTER];
// transposed split weights: [E][N][K] K-major bf16
__device__ __nv_bfloat16 g_w1t_hi[(size_t)NUM_EXPERTS * INTER * HIDDEN];
__device__ __nv_bfloat16 g_w1t_lo[(size_t)NUM_EXPERTS * INTER * HIDDEN];
__device__ __nv_bfloat16 g_w2t_hi[(size_t)NUM_EXPERTS * HIDDEN * INTER];
__device__ __nv_bfloat16 g_w2t_lo[(size_t)NUM_EXPERTS * HIDDEN * INTER];

// ---------------- helpers ----------------
__device__ __forceinline__ unsigned smem_u32(const void* p) {
    unsigned a;
    asm("{ .reg .u64 t; cvta.to.shared.u64 t, %1; cvt.u32.u64 %0, t; }"
        : "=r"(a) : "l"(p));
    return a;
}
__device__ __forceinline__ unsigned sw128(unsigned off) {
    return off ^ ((off >> 3) & 0x70);
}
__device__ __forceinline__ unsigned pack2_hi(float a, float b,
                                             __nv_bfloat16& ha, __nv_bfloat16& hb) {
    ha = __float2bfloat16(a);
    hb = __float2bfloat16(b);
    return (unsigned)__bfloat16_as_ushort(ha) | ((unsigned)__bfloat16_as_ushort(hb) << 16);
}
__device__ __forceinline__ float gelu_tanh(float x) {
    const float c = 0.7978845608028654f;
    float x3 = x * x * x;
    return 0.5f * x * (1.0f + tanhf(c * (x + 0.044715f * x3)));
}

#define CP16(dst, src, nbytes) \
    asm volatile("cp.async.cg.shared.global [%0], [%1], 16, %2;" \
        :: "r"(dst), "l"(src), "r"((unsigned)(nbytes)) : "memory")
#define CP_COMMIT() asm volatile("cp.async.commit_group;" ::: "memory")
#define CP_WAIT0()  asm volatile("cp.async.wait_group 0;" ::: "memory")

#define LDSM4(r, addr) \
    asm volatile("ldmatrix.sync.aligned.m8n8.x4.shared.b16 {%0,%1,%2,%3}, [%4];" \
        : "=r"((r)[0]), "=r"((r)[1]), "=r"((r)[2]), "=r"((r)[3]) : "r"(addr))

#define MMA16816(c, a, b0v, b1v) \
    asm volatile("mma.sync.aligned.m16n8k16.row.col.f32.bf16.bf16.f32 " \
        "{%0,%1,%2,%3}, {%4,%5,%6,%7}, {%8,%9}, {%0,%1,%2,%3};" \
        : "+f"((c)[0]), "+f"((c)[1]), "+f"((c)[2]), "+f"((c)[3]) \
        : "r"((a)[0]), "r"((a)[1]), "r"((a)[2]), "r"((a)[3]), "r"(b0v), "r"(b1v))

// ---------------- kernel 0: reset ----------------
__global__ void reset_kernel() {
    int t = threadIdx.x;
    if (t < NUM_EXPERTS) g_cnt[t] = 0;
}

// ---------------- kernel: split activations ----------------
__global__ void split_x_kernel(const float* __restrict__ hidden) {
    int i = blockIdx.x * 256 + threadIdx.x;       // one float4 per thread
    float4 v = *(const float4*)&hidden[(size_t)i * 4];
    __nv_bfloat16 h0, h1, h2, h3;
    unsigned hp0 = pack2_hi(v.x, v.y, h0, h1);
    unsigned hp1 = pack2_hi(v.z, v.w, h2, h3);
    __nv_bfloat16 d0, d1, d2, d3;
    unsigned lp0 = pack2_hi(v.x - __bfloat162float(h0), v.y - __bfloat162float(h1), d0, d1);
    unsigned lp1 = pack2_hi(v.z - __bfloat162float(h2), v.w - __bfloat162float(h3), d2, d3);
    *(uint2*)&g_xh[(size_t)i * 4] = make_uint2(hp0, hp1);
    *(uint2*)&g_xl[(size_t)i * 4] = make_uint2(lp0, lp1);
}

// ---------------- kernel 1: router ----------------
__global__ void router_kernel(const float* __restrict__ hidden,
                              const float* __restrict__ w_router,
                              const float* __restrict__ b_router) {
    __shared__ float wsm[NUM_EXPERTS][HIDDEN];
    int tid = threadIdx.x;
    for (int i = tid; i < NUM_EXPERTS * HIDDEN; i += blockDim.x) {
        int e = i / HIDDEN, h = i % HIDDEN;
        wsm[e][h] = w_router[h * NUM_EXPERTS + e];
    }
    __syncthreads();

    int warp = tid >> 5, lane = tid & 31;
    int t = blockIdx.x * (blockDim.x >> 5) + warp;
    if (t >= NTOK) return;

    const float* x = hidden + (size_t)t * HIDDEN;
    float acc[NUM_EXPERTS];
#pragma unroll
    for (int e = 0; e < NUM_EXPERTS; e++) acc[e] = 0.f;
    for (int i = lane; i < HIDDEN; i += 32) {
        float xv = x[i];
#pragma unroll
        for (int e = 0; e < NUM_EXPERTS; e++) acc[e] += xv * wsm[e][i];
    }
#pragma unroll
    for (int off = 16; off > 0; off >>= 1) {
#pragma unroll
        for (int e = 0; e < NUM_EXPERTS; e++)
            acc[e] += __shfl_xor_sync(0xffffffffu, acc[e], off);
    }
    if (lane == 0) {
        float logits[NUM_EXPERTS], mx = -1e30f;
#pragma unroll
        for (int e = 0; e < NUM_EXPERTS; e++) {
            logits[e] = acc[e] + b_router[e];
            mx = fmaxf(mx, logits[e]);
        }
        float p[NUM_EXPERTS], Z = 0.f;
#pragma unroll
        for (int e = 0; e < NUM_EXPERTS; e++) { p[e] = __expf(logits[e] - mx); Z += p[e]; }
        float invZ = 1.0f / Z;
#pragma unroll
        for (int e = 0; e < NUM_EXPERTS; e++) {
            p[e] *= invZ;
            g_probs[t * NUM_EXPERTS + e] = p[e];
        }
        int i1 = 0; float p1 = p[0];
#pragma unroll
        for (int e = 1; e < NUM_EXPERTS; e++) if (p[e] > p1) { p1 = p[e]; i1 = e; }
        int i2 = -1; float p2 = -1.0f;
#pragma unroll
        for (int e = 0; e < NUM_EXPERTS; e++)
            if (e != i1 && p[e] > p2) { p2 = p[e]; i2 = e; }
        float rs = 1.0f / (p1 + p2);
        int pos1 = atomicAdd(&g_cnt[i1], 1);
        g_tok[i1][pos1] = t; g_wt[i1][pos1] = p1 * rs;
        int pos2 = atomicAdd(&g_cnt[i2], 1);
        g_tok[i2][pos2] = t; g_wt[i2][pos2] = p2 * rs;
    }
}

// ---------------- kernel 2: balance loss ----------------
__global__ void loss_kernel(float* __restrict__ out, int write_loss) {
    __shared__ float red[256];
    int tid = threadIdx.x;
    float loss_acc = 0.f;
    for (int e = 0; e < NUM_EXPERTS; e++) {
        float s = 0.f;
        for (int t = tid; t < NTOK; t += 256)
            s += g_probs[t * NUM_EXPERTS + e];
        red[tid] = s;
        __syncthreads();
        for (int off = 128; off > 0; off >>= 1) {
            if (tid < off) red[tid] += red[tid + off];
            __syncthreads();
        }
        if (tid == 0) {
            float P = red[0] / (float)NTOK;
            float f = (float)g_cnt[e] / (float)NSLOT;
            loss_acc += f * P;
        }
        __syncthreads();
    }
    if (tid == 0 && write_loss)
        out[(size_t)NTOK * HIDDEN] = 0.01f * (float)NUM_EXPERTS * loss_acc;
}

// ---------------- kernel 3: transpose + split weights ----------------
// w: [E][K][N] fp32 -> hi/lo: [E][N][K] bf16.  64-k x 32-n tiles, packed stores.
__global__ void transpose_split_kernel(const float* __restrict__ w,
                                       int which, int K, int N) {
    __nv_bfloat16* hi = which ? g_w2t_hi : g_w1t_hi;
    __nv_bfloat16* lo = which ? g_w2t_lo : g_w1t_lo;
    __shared__ float tile[64][33];
    int e = blockIdx.z;
    int n0 = blockIdx.x * 32, k0 = blockIdx.y * 64;
    const float* we = w + (size_t)e * K * N;
    int tx = threadIdx.x, ty = threadIdx.y; // 32 x 8
#pragma unroll
    for (int r = 0; r < 8; r++) {
        int kl = ty + r * 8;
        tile[kl][tx] = we[(size_t)(k0 + kl) * N + n0 + tx];
    }
    __syncthreads();
#pragma unroll
    for (int r = 0; r < 4; r++) {
        int nl = ty + r * 8;
        float v0 = tile[2 * tx][nl];
        float v1 = tile[2 * tx + 1][nl];
        __nv_bfloat16 h0, h1;
        unsigned hp = pack2_hi(v0, v1, h0, h1);
        __nv_bfloat16 d0, d1;
        unsigned lp = pack2_hi(v0 - __bfloat162float(h0), v1 - __bfloat162float(h1), d0, d1);
        size_t o = ((size_t)e * N + n0 + nl) * K + k0 + 2 * tx;
        *(unsigned*)&hi[o] = hp;
        *(unsigned*)&lo[o] = lp;
    }
}

// ======================================================================
// GEMM1: hmid = gelu(gather(x) @ w1 + b1). CTA 128x128, cp.async 2-stage.
// 8 warps (2m x 4n), warp tile 64x32, 3-way bf16 split.
// ======================================================================
#define G1_STAGE 65536
__global__ void __launch_bounds__(256)
gemm1_mma(const float* __restrict__ b1) {
    int e = blockIdx.z;
    int cnt = g_cnt[e];
    int m0 = blockIdx.y * 128;
    if (m0 >= cnt) return;
    int n0 = blockIdx.x * 128;

    extern __shared__ char dsm[];
    unsigned sb = smem_u32(dsm);
    unsigned base = (sb + 1023u) & ~1023u;

    __shared__ int toks[128];
    int tid = threadIdx.x, wid = tid >> 5, lane = tid & 31;
    if (tid < 128) toks[tid] = (m0 + tid < cnt) ? g_tok[e][m0 + tid] : -1;
    __syncthreads();

    const __nv_bfloat16* w1h = g_w1t_hi + (size_t)e * INTER * HIDDEN;
    const __nv_bfloat16* w1l = g_w1t_lo + (size_t)e * INTER * HIDDEN;

    int wm = wid >> 2, wn = wid & 3;
    int rA = (lane & 7) + 8 * ((lane >> 3) & 1);
    int cA = lane >> 4;
    int rB = (lane & 7) + 8 * (lane >> 4);
    int cB = (lane >> 3) & 1;

    float acc[4][4][4];
#pragma unroll
    for (int i = 0; i < 4; i++)
#pragma unroll
        for (int j = 0; j < 4; j++)
#pragma unroll
            for (int q = 0; q < 4; q++) acc[i][j][q] = 0.f;

    const int KT = HIDDEN / BKC; // 8

    // issue one chunk into stage s
    auto issue = [&](int kt, int s) {
        unsigned st = base + s * G1_STAGE;
        int k0 = kt * BKC;
#pragma unroll
        for (int u = 0; u < 4; u++) {
            int idx = tid + u * 256;
            int row = idx >> 3, seg = idx & 7;
            unsigned so = sw128((unsigned)(row * 128 + seg * 16));
            int tok = toks[row];
            const __nv_bfloat16* sh = (tok >= 0) ? g_xh + (size_t)tok * HIDDEN + k0 + seg * 8 : g_xh;
            const __nv_bfloat16* sl = (tok >= 0) ? g_xl + (size_t)tok * HIDDEN + k0 + seg * 8 : g_xl;
            unsigned pb = (tok >= 0) ? 16u : 0u;
            CP16(st + so, sh, pb);
            CP16(st + 16384 + so, sl, pb);
            size_t bsrc = (size_t)(n0 + row) * HIDDEN + k0 + seg * 8;
            CP16(st + 32768 + so, w1h + bsrc, 16u);
            CP16(st + 49152 + so, w1l + bsrc, 16u);
        }
        CP_COMMIT();
    };

    issue(0, 0);
    for (int kt = 0; kt < KT; kt++) {
        CP_WAIT0();
        __syncthreads();
        if (kt + 1 < KT) issue(kt + 1, (kt + 1) & 1);
        unsigned st = base + (kt & 1) * G1_STAGE;
        unsigned uAh = st, uAl = st + 16384, uBh = st + 32768, uBl = st + 49152;
#pragma unroll
        for (int k16 = 0; k16 < 4; k16++) {
            unsigned Afh[4][4], Afl[4][4], Bf[2][4];
#pragma unroll
            for (int mt = 0; mt < 4; mt++) {
                unsigned off = sw128((unsigned)((64 * wm + 16 * mt + rA) * 128 + (2 * k16 + cA) * 16));
                LDSM4(Afh[mt], uAh + off);
                LDSM4(Afl[mt], uAl + off);
            }
#pragma unroll
            for (int pr = 0; pr < 2; pr++) {
                unsigned off = sw128((unsigned)((32 * wn + 16 * pr + rB) * 128 + (2 * k16 + cB) * 16));
                LDSM4(Bf[pr], uBh + off);
            }
#pragma unroll
            for (int mt = 0; mt < 4; mt++)
#pragma unroll
                for (int nt = 0; nt < 4; nt++) {
                    unsigned b0 = Bf[nt >> 1][(nt & 1) * 2], b1v = Bf[nt >> 1][(nt & 1) * 2 + 1];
                    MMA16816(acc[mt][nt], Afh[mt], b0, b1v);
                }
#pragma unroll
            for (int mt = 0; mt < 4; mt++)
#pragma unroll
                for (int nt = 0; nt < 4; nt++) {
                    unsigned b0 = Bf[nt >> 1][(nt & 1) * 2], b1v = Bf[nt >> 1][(nt & 1) * 2 + 1];
                    MMA16816(acc[mt][nt], Afl[mt], b0, b1v);
                }
#pragma unroll
            for (int pr = 0; pr < 2; pr++) {
                unsigned off = sw128((unsigned)((32 * wn + 16 * pr + rB) * 128 + (2 * k16 + cB) * 16));
                LDSM4(Bf[pr], uBl + off);
            }
#pragma unroll
            for (int mt = 0; mt < 4; mt++)
#pragma unroll
                for (int nt = 0; nt < 4; nt++) {
                    unsigned b0 = Bf[nt >> 1][(nt & 1) * 2], b1v = Bf[nt >> 1][(nt & 1) * 2 + 1];
                    MMA16816(acc[mt][nt], Afh[mt], b0, b1v);
                }
        }
        __syncthreads();
    }

    // epilogue: bias + gelu, write hmid hi/lo planes
    int g = lane >> 2, tg = lane & 3;
#pragma unroll
    for (int mt = 0; mt < 4; mt++) {
        int mA = m0 + 64 * wm + 16 * mt + g;
        int mB = mA + 8;
#pragma unroll
        for (int nt = 0; nt < 4; nt++) {
            int n = n0 + 32 * wn + 8 * nt + 2 * tg;
            float2 bb = *(const float2*)&b1[(size_t)e * INTER + n];
            if (mA < cnt) {
                float v0 = gelu_tanh(acc[mt][nt][0] + bb.x);
                float v1 = gelu_tanh(acc[mt][nt][1] + bb.y);
                __nv_bfloat16 h0, h1, d0, d1;
                unsigned hp = pack2_hi(v0, v1, h0, h1);
                unsigned lp = pack2_hi(v0 - __bfloat162float(h0), v1 - __bfloat162float(h1), d0, d1);
                size_t o = ((size_t)e * MAXROWS + mA) * INTER + n;
                *(unsigned*)&g_hmid_hi[o] = hp;
                *(unsigned*)&g_hmid_lo[o] = lp;
            }
            if (mB < cnt) {
                float v2 = gelu_tanh(acc[mt][nt][2] + bb.x);
                float v3 = gelu_tanh(acc[mt][nt][3] + bb.y);
                __nv_bfloat16 h2, h3, d2, d3;
                unsigned hp = pack2_hi(v2, v3, h2, h3);
                unsigned lp = pack2_hi(v2 - __bfloat162float(h2), v3 - __bfloat162float(h3), d2, d3);
                size_t o = ((size_t)e * MAXROWS + mB) * INTER + n;
                *(unsigned*)&g_hmid_hi[o] = hp;
                *(unsigned*)&g_hmid_lo[o] = lp;
            }
        }
    }
}

// ======================================================================
// GEMM2: out[tok] += wt*(hmid @ w2 + b2). CTA 128x64, cp.async 2-stage.
// 8 warps (2m x 4n), warp tile 64x16, 3-way bf16 split.
// ======================================================================
#define G2_STAGE 49152
__global__ void __launch_bounds__(256, 2)
gemm2_mma(const float* __restrict__ b2, float* __restrict__ out) {
    int e = blockIdx.z;
    int cnt = g_cnt[e];
    int m0 = blockIdx.y * 128;
    if (m0 >= cnt) return;
    int n0 = blockIdx.x * 64;

    extern __shared__ char dsm[];
    unsigned sb = smem_u32(dsm);
    unsigned base = (sb + 1023u) & ~1023u;

    int tid = threadIdx.x, wid = tid >> 5, lane = tid & 31;
    int wm = wid >> 2, wn = wid & 3;
    int rA = (lane & 7) + 8 * ((lane >> 3) & 1);
    int cA = lane >> 4;
    int rB = (lane & 7) + 8 * (lane >> 4);
    int cB = (lane >> 3) & 1;

    const __nv_bfloat16* w2h = g_w2t_hi + (size_t)e * HIDDEN * INTER;
    const __nv_bfloat16* w2l = g_w2t_lo + (size_t)e * HIDDEN * INTER;
    const __nv_bfloat16* ah = g_hmid_hi + (size_t)e * MAXROWS * INTER;
    const __nv_bfloat16* al = g_hmid_lo + (size_t)e * MAXROWS * INTER;

    float acc[4][2][4];
#pragma unroll
    for (int i = 0; i < 4; i++)
#pragma unroll
        for (int j = 0; j < 2; j++)
#pragma unroll
            for (int q = 0; q < 4; q++) acc[i][j][q] = 0.f;

    const int KT = INTER / BKC; // 32

    auto issue = [&](int kt, int s) {
        unsigned st = base + s * G2_STAGE;
        int k0 = kt * BKC;
#pragma unroll
        for (int u = 0; u < 4; u++) {
            int idx = tid + u * 256;
            int row = idx >> 3, seg = idx & 7;
            unsigned so = sw128((unsigned)(row * 128 + seg * 16));
            int gm = m0 + row;
            size_t asrc = (size_t)gm * INTER + k0 + seg * 8;
            unsigned pb = (gm < cnt) ? 16u : 0u;
            const __nv_bfloat16* sh = (gm < cnt) ? ah + asrc : ah;
            const __nv_bfloat16* sl = (gm < cnt) ? al + asrc : al;
            CP16(st + so, sh, pb);
            CP16(st + 16384 + so, sl, pb);
        }
#pragma unroll
        for (int u = 0; u < 2; u++) {
            int idx = tid + u * 256;
            int row = idx >> 3, seg = idx & 7;
            unsigned so = sw128((unsigned)(row * 128 + seg * 16));
            size_t bsrc = (size_t)(n0 + row) * INTER + k0 + seg * 8;
            CP16(st + 32768 + so, w2h + bsrc, 16u);
            CP16(st + 40960 + so, w2l + bsrc, 16u);
        }
        CP_COMMIT();
    };

    issue(0, 0);
    for (int kt = 0; kt < KT; kt++) {
        CP_WAIT0();
        __syncthreads();
        if (kt + 1 < KT) issue(kt + 1, (kt + 1) & 1);
        unsigned st = base + (kt & 1) * G2_STAGE;
        unsigned uAh = st, uAl = st + 16384, uBh = st + 32768, uBl = st + 40960;
#pragma unroll
        for (int k16 = 0; k16 < 4; k16++) {
            unsigned Afh[4][4], Afl[4][4], Bf[4];
#pragma unroll
            for (int mt = 0; mt < 4; mt++) {
                unsigned off = sw128((unsigned)((64 * wm + 16 * mt + rA) * 128 + (2 * k16 + cA) * 16));
                LDSM4(Afh[mt], uAh + off);
                LDSM4(Afl[mt], uAl + off);
            }
            {
                unsigned off = sw128((unsigned)((16 * wn + rB) * 128 + (2 * k16 + cB) * 16));
                LDSM4(Bf, uBh + off);
            }
#pragma unroll
            for (int mt = 0; mt < 4; mt++)
#pragma unroll
                for (int nt = 0; nt < 2; nt++)
                    MMA16816(acc[mt][nt], Afh[mt], Bf[nt * 2], Bf[nt * 2 + 1]);
#pragma unroll
            for (int mt = 0; mt < 4; mt++)
#pragma unroll
                for (int nt = 0; nt < 2; nt++)
                    MMA16816(acc[mt][nt], Afl[mt], Bf[nt * 2], Bf[nt * 2 + 1]);
            {
                unsigned off = sw128((unsigned)((16 * wn + rB) * 128 + (2 * k16 + cB) * 16));
                LDSM4(Bf, uBl + off);
            }
#pragma unroll
            for (int mt = 0; mt < 4; mt++)
#pragma unroll
                for (int nt = 0; nt < 2; nt++)
                    MMA16816(acc[mt][nt], Afh[mt], Bf[nt * 2], Bf[nt * 2 + 1]);
        }
        __syncthreads();
    }

    // epilogue: weighted atomic accumulate onto residual out
    int g = lane >> 2, tg = lane & 3;
#pragma unroll
    for (int mt = 0; mt < 4; mt++) {
        int mA = m0 + 64 * wm + 16 * mt + g;
        int mB = mA + 8;
        float wA = (mA < cnt) ? g_wt[e][mA] : 0.f;
        float wB = (mB < cnt) ? g_wt[e][mB] : 0.f;
        int tokA = (mA < cnt) ? g_tok[e][mA] : 0;
        int tokB = (mB < cnt) ? g_tok[e][mB] : 0;
#pragma unroll
        for (int nt = 0; nt < 2; nt++) {
            int n = n0 + 16 * wn + 8 * nt + 2 * tg;
            float2 bb = *(const float2*)&b2[(size_t)e * HIDDEN + n];
            if (mA < cnt) {
                float* op = out + (size_t)tokA * HIDDEN + n;
                atomicAdd(op,     (acc[mt][nt][0] + bb.x) * wA);
                atomicAdd(op + 1, (acc[mt][nt][1] + bb.y) * wA);
            }
            if (mB < cnt) {
                float* op = out + (size_t)tokB * HIDDEN + n;
                atomicAdd(op,     (acc[mt][nt][2] + bb.x) * wB);
                atomicAdd(op + 1, (acc[mt][nt][3] + bb.y) * wB);
            }
        }
    }
}

// ---------------- launch ----------------
extern "C" void kernel_launch(void* const* d_in, const int* in_sizes, int n_in,
                              void* d_out, int out_size) {
    const float* hidden   = (const float*)d_in[0];
    const float* w_router = (const float*)d_in[1];
    const float* b_router = (const float*)d_in[2];
    const float* w1       = (const float*)d_in[3];
    const float* b1       = (const float*)d_in[4];
    const float* w2       = (const float*)d_in[5];
    const float* b2       = (const float*)d_in[6];
    float* out = (float*)d_out;

    const int SMEM1 = 2 * G1_STAGE + 1024;  // 132096
    const int SMEM2 = 2 * G2_STAGE + 1024;  // 99328
    cudaFuncSetAttribute(gemm1_mma, cudaFuncAttributeMaxDynamicSharedMemorySize, SMEM1);
    cudaFuncSetAttribute(gemm2_mma, cudaFuncAttributeMaxDynamicSharedMemorySize, SMEM2);

    // residual init
    cudaMemcpyAsync(out, hidden, (size_t)NTOK * HIDDEN * sizeof(float),
                    cudaMemcpyDeviceToDevice);

    reset_kernel<<<1, 32>>>();
    router_kernel<<<NTOK / 8, 256>>>(hidden, w_router, b_router);

    int write_loss = (out_size > NTOK * HIDDEN) ? 1 : 0;
    loss_kernel<<<1, 256>>>(out, write_loss);

    split_x_kernel<<<NTOK * HIDDEN / 1024, 256>>>(hidden);
    transpose_split_kernel<<<dim3(INTER / 32, HIDDEN / 64, NUM_EXPERTS), dim3(32, 8)>>>(
        w1, 0, HIDDEN, INTER);
    transpose_split_kernel<<<dim3(HIDDEN / 32, INTER / 64, NUM_EXPERTS), dim3(32, 8)>>>(
        w2, 1, INTER, HIDDEN);

    gemm1_mma<<<dim3(INTER / 128, MAXROWS / 128, NUM_EXPERTS), 256, SMEM1>>>(b1);
    gemm2_mma<<<dim3(HIDDEN / 64, MAXROWS / 128, NUM_EXPERTS), 256, SMEM2>>>(b2, out);
}

// round 11
// speedup vs baseline: 4.2286x; 1.0844x over previous
#include <cuda_runtime.h>
#include <cuda_bf16.h>
#include <math.h>

// Problem constants
#define NUM_EXPERTS 8
#define TOP_K 2
#define HIDDEN 512
#define INTER 2048
#define NTOK 2048
#define NSLOT (NTOK * TOP_K)
#define MAXROWS 2048

#define BKC 64            // k per chunk (128 B bf16 rows)
#define G_STAGE 49152     // per-stage smem: A hi/lo 32K + B hi/lo 16K

// ---------------- device scratch ----------------
__device__ int   g_cnt[NUM_EXPERTS];
__device__ int   g_tok[NUM_EXPERTS][MAXROWS];
__device__ float g_wt[NUM_EXPERTS][MAXROWS];
__device__ float g_probs[NTOK * NUM_EXPERTS];
__device__ __nv_bfloat16 g_xh[(size_t)NTOK * HIDDEN];
__device__ __nv_bfloat16 g_xl[(size_t)NTOK * HIDDEN];
__device__ __nv_bfloat16 g_hmid_hi[(size_t)NUM_EXPERTS * MAXROWS * INTER];
__device__ __nv_bfloat16 g_hmid_lo[(size_t)NUM_EXPERTS * MAXROWS * INTER];
__device__ __nv_bfloat16 g_w1t_hi[(size_t)NUM_EXPERTS * INTER * HIDDEN];
__device__ __nv_bfloat16 g_w1t_lo[(size_t)NUM_EXPERTS * INTER * HIDDEN];
__device__ __nv_bfloat16 g_w2t_hi[(size_t)NUM_EXPERTS * HIDDEN * INTER];
__device__ __nv_bfloat16 g_w2t_lo[(size_t)NUM_EXPERTS * HIDDEN * INTER];

// ---------------- host-side streams/events (static init, pre-checkpoint) ----
struct ForkJoin {
    cudaStream_t s1, s2;
    cudaEvent_t evRoot, evW1, evW2;
    ForkJoin() {
        cudaStreamCreateWithFlags(&s1, cudaStreamNonBlocking);
        cudaStreamCreateWithFlags(&s2, cudaStreamNonBlocking);
        cudaEventCreateWithFlags(&evRoot, cudaEventDisableTiming);
        cudaEventCreateWithFlags(&evW1, cudaEventDisableTiming);
        cudaEventCreateWithFlags(&evW2, cudaEventDisableTiming);
    }
};
static ForkJoin g_fj;

// ---------------- helpers ----------------
__device__ __forceinline__ unsigned smem_u32(const void* p) {
    unsigned a;
    asm("{ .reg .u64 t; cvta.to.shared.u64 t, %1; cvt.u32.u64 %0, t; }"
        : "=r"(a) : "l"(p));
    return a;
}
__device__ __forceinline__ unsigned sw128(unsigned off) {
    return off ^ ((off >> 3) & 0x70);
}
__device__ __forceinline__ unsigned pack2_hi(float a, float b,
                                             __nv_bfloat16& ha, __nv_bfloat16& hb) {
    ha = __float2bfloat16(a);
    hb = __float2bfloat16(b);
    return (unsigned)__bfloat16_as_ushort(ha) | ((unsigned)__bfloat16_as_ushort(hb) << 16);
}
__device__ __forceinline__ float gelu_tanh(float x) {
    const float c = 0.7978845608028654f;
    float x3 = x * x * x;
    return 0.5f * x * (1.0f + tanhf(c * (x + 0.044715f * x3)));
}

#define CP16(dst, src, nbytes) \
    asm volatile("cp.async.cg.shared.global [%0], [%1], 16, %2;" \
        :: "r"(dst), "l"(src), "r"((unsigned)(nbytes)) : "memory")
#define CP_COMMIT() asm volatile("cp.async.commit_group;" ::: "memory")
#define CP_WAIT0()  asm volatile("cp.async.wait_group 0;" ::: "memory")

#define LDSM4(r, addr) \
    asm volatile("ldmatrix.sync.aligned.m8n8.x4.shared.b16 {%0,%1,%2,%3}, [%4];" \
        : "=r"((r)[0]), "=r"((r)[1]), "=r"((r)[2]), "=r"((r)[3]) : "r"(addr))

#define MMA16816(c, a, b0v, b1v) \
    asm volatile("mma.sync.aligned.m16n8k16.row.col.f32.bf16.bf16.f32 " \
        "{%0,%1,%2,%3}, {%4,%5,%6,%7}, {%8,%9}, {%0,%1,%2,%3};" \
        : "+f"((c)[0]), "+f"((c)[1]), "+f"((c)[2]), "+f"((c)[3]) \
        : "r"((a)[0]), "r"((a)[1]), "r"((a)[2]), "r"((a)[3]), "r"(b0v), "r"(b1v))

// ---------------- kernel 0: reset ----------------
__global__ void reset_kernel() {
    int t = threadIdx.x;
    if (t < NUM_EXPERTS) g_cnt[t] = 0;
}

// ---------------- kernel 1: router (+ fused activation split) ----------------
__global__ void router_kernel(const float* __restrict__ hidden,
                              const float* __restrict__ w_router,
                              const float* __restrict__ b_router) {
    __shared__ float wsm[NUM_EXPERTS][HIDDEN];
    int tid = threadIdx.x;

    // fused split: this block owns tokens [blockIdx.x*8, +8) = 4096 floats
    {
        size_t base = (size_t)blockIdx.x * 8 * HIDDEN;
#pragma unroll
        for (int u = 0; u < 4; u++) {
            size_t idx = base + ((size_t)(tid + u * 256)) * 4;
            float4 v = *(const float4*)&hidden[idx];
            __nv_bfloat16 h0, h1, h2, h3, d0, d1, d2, d3;
            unsigned hp0 = pack2_hi(v.x, v.y, h0, h1);
            unsigned hp1 = pack2_hi(v.z, v.w, h2, h3);
            unsigned lp0 = pack2_hi(v.x - __bfloat162float(h0), v.y - __bfloat162float(h1), d0, d1);
            unsigned lp1 = pack2_hi(v.z - __bfloat162float(h2), v.w - __bfloat162float(h3), d2, d3);
            *(uint2*)&g_xh[idx] = make_uint2(hp0, hp1);
            *(uint2*)&g_xl[idx] = make_uint2(lp0, lp1);
        }
    }

    for (int i = tid; i < NUM_EXPERTS * HIDDEN; i += blockDim.x) {
        int e = i / HIDDEN, h = i % HIDDEN;
        wsm[e][h] = w_router[h * NUM_EXPERTS + e];
    }
    __syncthreads();

    int warp = tid >> 5, lane = tid & 31;
    int t = blockIdx.x * 8 + warp;
    if (t >= NTOK) return;

    const float* x = hidden + (size_t)t * HIDDEN;
    float acc[NUM_EXPERTS];
#pragma unroll
    for (int e = 0; e < NUM_EXPERTS; e++) acc[e] = 0.f;
    for (int i = lane; i < HIDDEN; i += 32) {
        float xv = x[i];
#pragma unroll
        for (int e = 0; e < NUM_EXPERTS; e++) acc[e] += xv * wsm[e][i];
    }
#pragma unroll
    for (int off = 16; off > 0; off >>= 1) {
#pragma unroll
        for (int e = 0; e < NUM_EXPERTS; e++)
            acc[e] += __shfl_xor_sync(0xffffffffu, acc[e], off);
    }
    if (lane == 0) {
        float logits[NUM_EXPERTS], mx = -1e30f;
#pragma unroll
        for (int e = 0; e < NUM_EXPERTS; e++) {
            logits[e] = acc[e] + b_router[e];
            mx = fmaxf(mx, logits[e]);
        }
        float p[NUM_EXPERTS], Z = 0.f;
#pragma unroll
        for (int e = 0; e < NUM_EXPERTS; e++) { p[e] = __expf(logits[e] - mx); Z += p[e]; }
        float invZ = 1.0f / Z;
#pragma unroll
        for (int e = 0; e < NUM_EXPERTS; e++) {
            p[e] *= invZ;
            g_probs[t * NUM_EXPERTS + e] = p[e];
        }
        int i1 = 0; float p1 = p[0];
#pragma unroll
        for (int e = 1; e < NUM_EXPERTS; e++) if (p[e] > p1) { p1 = p[e]; i1 = e; }
        int i2 = -1; float p2 = -1.0f;
#pragma unroll
        for (int e = 0; e < NUM_EXPERTS; e++)
            if (e != i1 && p[e] > p2) { p2 = p[e]; i2 = e; }
        float rs = 1.0f / (p1 + p2);
        int pos1 = atomicAdd(&g_cnt[i1], 1);
        g_tok[i1][pos1] = t; g_wt[i1][pos1] = p1 * rs;
        int pos2 = atomicAdd(&g_cnt[i2], 1);
        g_tok[i2][pos2] = t; g_wt[i2][pos2] = p2 * rs;
    }
}

// ---------------- kernel 2: balance loss ----------------
__global__ void loss_kernel(float* __restrict__ out, int write_loss) {
    __shared__ float red[256];
    int tid = threadIdx.x;
    float loss_acc = 0.f;
    for (int e = 0; e < NUM_EXPERTS; e++) {
        float s = 0.f;
        for (int t = tid; t < NTOK; t += 256)
            s += g_probs[t * NUM_EXPERTS + e];
        red[tid] = s;
        __syncthreads();
        for (int off = 128; off > 0; off >>= 1) {
            if (tid < off) red[tid] += red[tid + off];
            __syncthreads();
        }
        if (tid == 0) {
            float P = red[0] / (float)NTOK;
            float f = (float)g_cnt[e] / (float)NSLOT;
            loss_acc += f * P;
        }
        __syncthreads();
    }
    if (tid == 0 && write_loss)
        out[(size_t)NTOK * HIDDEN] = 0.01f * (float)NUM_EXPERTS * loss_acc;
}

// ---------------- kernel 3: transpose + split weights ----------------
__global__ void transpose_split_kernel(const float* __restrict__ w,
                                       int which, int K, int N) {
    __nv_bfloat16* hi = which ? g_w2t_hi : g_w1t_hi;
    __nv_bfloat16* lo = which ? g_w2t_lo : g_w1t_lo;
    __shared__ float tile[64][33];
    int e = blockIdx.z;
    int n0 = blockIdx.x * 32, k0 = blockIdx.y * 64;
    const float* we = w + (size_t)e * K * N;
    int tx = threadIdx.x, ty = threadIdx.y; // 32 x 8
#pragma unroll
    for (int r = 0; r < 8; r++) {
        int kl = ty + r * 8;
        tile[kl][tx] = we[(size_t)(k0 + kl) * N + n0 + tx];
    }
    __syncthreads();
#pragma unroll
    for (int r = 0; r < 4; r++) {
        int nl = ty + r * 8;
        float v0 = tile[2 * tx][nl];
        float v1 = tile[2 * tx + 1][nl];
        __nv_bfloat16 h0, h1, d0, d1;
        unsigned hp = pack2_hi(v0, v1, h0, h1);
        unsigned lp = pack2_hi(v0 - __bfloat162float(h0), v1 - __bfloat162float(h1), d0, d1);
        size_t o = ((size_t)e * N + n0 + nl) * K + k0 + 2 * tx;
        *(unsigned*)&hi[o] = hp;
        *(unsigned*)&lo[o] = lp;
    }
}

// ======================================================================
// GEMM1: hmid = gelu(gather(x) @ w1 + b1). CTA 128x64, cp.async 2-stage.
// 8 warps (2m x 4n), warp tile 64x16, 3-way bf16 split. 2 CTAs/SM.
// ======================================================================
__global__ void __launch_bounds__(256, 2)
gemm1_mma(const float* __restrict__ b1) {
    int e = blockIdx.z;
    int cnt = g_cnt[e];
    int m0 = blockIdx.y * 128;
    if (m0 >= cnt) return;
    int n0 = blockIdx.x * 64;

    extern __shared__ char dsm[];
    unsigned sb = smem_u32(dsm);
    unsigned base = (sb + 1023u) & ~1023u;

    __shared__ int toks[128];
    int tid = threadIdx.x, wid = tid >> 5, lane = tid & 31;
    if (tid < 128) toks[tid] = (m0 + tid < cnt) ? g_tok[e][m0 + tid] : -1;
    __syncthreads();

    const __nv_bfloat16* w1h = g_w1t_hi + (size_t)e * INTER * HIDDEN;
    const __nv_bfloat16* w1l = g_w1t_lo + (size_t)e * INTER * HIDDEN;

    int wm = wid >> 2, wn = wid & 3;
    int rA = (lane & 7) + 8 * ((lane >> 3) & 1);
    int cA = lane >> 4;
    int rB = (lane & 7) + 8 * (lane >> 4);
    int cB = (lane >> 3) & 1;

    float acc[4][2][4];
#pragma unroll
    for (int i = 0; i < 4; i++)
#pragma unroll
        for (int j = 0; j < 2; j++)
#pragma unroll
            for (int q = 0; q < 4; q++) acc[i][j][q] = 0.f;

    const int KT = HIDDEN / BKC; // 8

    auto issue = [&](int kt, int s) {
        unsigned st = base + s * G_STAGE;
        int k0 = kt * BKC;
#pragma unroll
        for (int u = 0; u < 4; u++) {
            int idx = tid + u * 256;
            int row = idx >> 3, seg = idx & 7;
            unsigned so = sw128((unsigned)(row * 128 + seg * 16));
            int tok = toks[row];
            const __nv_bfloat16* sh = (tok >= 0) ? g_xh + (size_t)tok * HIDDEN + k0 + seg * 8 : g_xh;
            const __nv_bfloat16* sl = (tok >= 0) ? g_xl + (size_t)tok * HIDDEN + k0 + seg * 8 : g_xl;
            unsigned pb = (tok >= 0) ? 16u : 0u;
            CP16(st + so, sh, pb);
            CP16(st + 16384 + so, sl, pb);
        }
#pragma unroll
        for (int u = 0; u < 2; u++) {
            int idx = tid + u * 256;
            int row = idx >> 3, seg = idx & 7;
            unsigned so = sw128((unsigned)(row * 128 + seg * 16));
            size_t bsrc = (size_t)(n0 + row) * HIDDEN + k0 + seg * 8;
            CP16(st + 32768 + so, w1h + bsrc, 16u);
            CP16(st + 40960 + so, w1l + bsrc, 16u);
        }
        CP_COMMIT();
    };

    issue(0, 0);
    for (int kt = 0; kt < KT; kt++) {
        CP_WAIT0();
        __syncthreads();
        if (kt + 1 < KT) issue(kt + 1, (kt + 1) & 1);
        unsigned st = base + (kt & 1) * G_STAGE;
        unsigned uAh = st, uAl = st + 16384, uBh = st + 32768, uBl = st + 40960;
#pragma unroll
        for (int k16 = 0; k16 < 4; k16++) {
            unsigned Afh[4][4], Afl[4][4], Bf[4];
#pragma unroll
            for (int mt = 0; mt < 4; mt++) {
                unsigned off = sw128((unsigned)((64 * wm + 16 * mt + rA) * 128 + (2 * k16 + cA) * 16));
                LDSM4(Afh[mt], uAh + off);
                LDSM4(Afl[mt], uAl + off);
            }
            {
                unsigned off = sw128((unsigned)((16 * wn + rB) * 128 + (2 * k16 + cB) * 16));
                LDSM4(Bf, uBh + off);
            }
#pragma unroll
            for (int mt = 0; mt < 4; mt++)
#pragma unroll
                for (int nt = 0; nt < 2; nt++)
                    MMA16816(acc[mt][nt], Afh[mt], Bf[nt * 2], Bf[nt * 2 + 1]);
#pragma unroll
            for (int mt = 0; mt < 4; mt++)
#pragma unroll
                for (int nt = 0; nt < 2; nt++)
                    MMA16816(acc[mt][nt], Afl[mt], Bf[nt * 2], Bf[nt * 2 + 1]);
            {
                unsigned off = sw128((unsigned)((16 * wn + rB) * 128 + (2 * k16 + cB) * 16));
                LDSM4(Bf, uBl + off);
            }
#pragma unroll
            for (int mt = 0; mt < 4; mt++)
#pragma unroll
                for (int nt = 0; nt < 2; nt++)
                    MMA16816(acc[mt][nt], Afh[mt], Bf[nt * 2], Bf[nt * 2 + 1]);
        }
        __syncthreads();
    }

    // epilogue: bias + gelu, split, write hmid hi/lo planes
    int g = lane >> 2, tg = lane & 3;
#pragma unroll
    for (int mt = 0; mt < 4; mt++) {
        int mA = m0 + 64 * wm + 16 * mt + g;
        int mB = mA + 8;
#pragma unroll
        for (int nt = 0; nt < 2; nt++) {
            int n = n0 + 16 * wn + 8 * nt + 2 * tg;
            float2 bb = *(const float2*)&b1[(size_t)e * INTER + n];
            if (mA < cnt) {
                float v0 = gelu_tanh(acc[mt][nt][0] + bb.x);
                float v1 = gelu_tanh(acc[mt][nt][1] + bb.y);
                __nv_bfloat16 h0, h1, d0, d1;
                unsigned hp = pack2_hi(v0, v1, h0, h1);
                unsigned lp = pack2_hi(v0 - __bfloat162float(h0), v1 - __bfloat162float(h1), d0, d1);
                size_t o = ((size_t)e * MAXROWS + mA) * INTER + n;
                *(unsigned*)&g_hmid_hi[o] = hp;
                *(unsigned*)&g_hmid_lo[o] = lp;
            }
            if (mB < cnt) {
                float v2 = gelu_tanh(acc[mt][nt][2] + bb.x);
                float v3 = gelu_tanh(acc[mt][nt][3] + bb.y);
                __nv_bfloat16 h2, h3, d2, d3;
                unsigned hp = pack2_hi(v2, v3, h2, h3);
                unsigned lp = pack2_hi(v2 - __bfloat162float(h2), v3 - __bfloat162float(h3), d2, d3);
                size_t o = ((size_t)e * MAXROWS + mB) * INTER + n;
                *(unsigned*)&g_hmid_hi[o] = hp;
                *(unsigned*)&g_hmid_lo[o] = lp;
            }
        }
    }
}

// ======================================================================
// GEMM2: out[tok] += wt*(hmid @ w2 + b2). CTA 128x64, cp.async 2-stage.
// ======================================================================
__global__ void __launch_bounds__(256, 2)
gemm2_mma(const float* __restrict__ b2, float* __restrict__ out) {
    int e = blockIdx.z;
    int cnt = g_cnt[e];
    int m0 = blockIdx.y * 128;
    if (m0 >= cnt) return;
    int n0 = blockIdx.x * 64;

    extern __shared__ char dsm[];
    unsigned sb = smem_u32(dsm);
    unsigned base = (sb + 1023u) & ~1023u;

    int tid = threadIdx.x, wid = tid >> 5, lane = tid & 31;
    int wm = wid >> 2, wn = wid & 3;
    int rA = (lane & 7) + 8 * ((lane >> 3) & 1);
    int cA = lane >> 4;
    int rB = (lane & 7) + 8 * (lane >> 4);
    int cB = (lane >> 3) & 1;

    const __nv_bfloat16* w2h = g_w2t_hi + (size_t)e * HIDDEN * INTER;
    const __nv_bfloat16* w2l = g_w2t_lo + (size_t)e * HIDDEN * INTER;
    const __nv_bfloat16* ah = g_hmid_hi + (size_t)e * MAXROWS * INTER;
    const __nv_bfloat16* al = g_hmid_lo + (size_t)e * MAXROWS * INTER;

    float acc[4][2][4];
#pragma unroll
    for (int i = 0; i < 4; i++)
#pragma unroll
        for (int j = 0; j < 2; j++)
#pragma unroll
            for (int q = 0; q < 4; q++) acc[i][j][q] = 0.f;

    const int KT = INTER / BKC; // 32

    auto issue = [&](int kt, int s) {
        unsigned st = base + s * G_STAGE;
        int k0 = kt * BKC;
#pragma unroll
        for (int u = 0; u < 4; u++) {
            int idx = tid + u * 256;
            int row = idx >> 3, seg = idx & 7;
            unsigned so = sw128((unsigned)(row * 128 + seg * 16));
            int gm = m0 + row;
            size_t asrc = (size_t)gm * INTER + k0 + seg * 8;
            unsigned pb = (gm < cnt) ? 16u : 0u;
            const __nv_bfloat16* sh = (gm < cnt) ? ah + asrc : ah;
            const __nv_bfloat16* sl = (gm < cnt) ? al + asrc : al;
            CP16(st + so, sh, pb);
            CP16(st + 16384 + so, sl, pb);
        }
#pragma unroll
        for (int u = 0; u < 2; u++) {
            int idx = tid + u * 256;
            int row = idx >> 3, seg = idx & 7;
            unsigned so = sw128((unsigned)(row * 128 + seg * 16));
            size_t bsrc = (size_t)(n0 + row) * INTER + k0 + seg * 8;
            CP16(st + 32768 + so, w2h + bsrc, 16u);
            CP16(st + 40960 + so, w2l + bsrc, 16u);
        }
        CP_COMMIT();
    };

    issue(0, 0);
    for (int kt = 0; kt < KT; kt++) {
        CP_WAIT0();
        __syncthreads();
        if (kt + 1 < KT) issue(kt + 1, (kt + 1) & 1);
        unsigned st = base + (kt & 1) * G_STAGE;
        unsigned uAh = st, uAl = st + 16384, uBh = st + 32768, uBl = st + 40960;
#pragma unroll
        for (int k16 = 0; k16 < 4; k16++) {
            unsigned Afh[4][4], Afl[4][4], Bf[4];
#pragma unroll
            for (int mt = 0; mt < 4; mt++) {
                unsigned off = sw128((unsigned)((64 * wm + 16 * mt + rA) * 128 + (2 * k16 + cA) * 16));
                LDSM4(Afh[mt], uAh + off);
                LDSM4(Afl[mt], uAl + off);
            }
            {
                unsigned off = sw128((unsigned)((16 * wn + rB) * 128 + (2 * k16 + cB) * 16));
                LDSM4(Bf, uBh + off);
            }
#pragma unroll
            for (int mt = 0; mt < 4; mt++)
#pragma unroll
                for (int nt = 0; nt < 2; nt++)
                    MMA16816(acc[mt][nt], Afh[mt], Bf[nt * 2], Bf[nt * 2 + 1]);
#pragma unroll
            for (int mt = 0; mt < 4; mt++)
#pragma unroll
                for (int nt = 0; nt < 2; nt++)
                    MMA16816(acc[mt][nt], Afl[mt], Bf[nt * 2], Bf[nt * 2 + 1]);
            {
                unsigned off = sw128((unsigned)((16 * wn + rB) * 128 + (2 * k16 + cB) * 16));
                LDSM4(Bf, uBl + off);
            }
#pragma unroll
            for (int mt = 0; mt < 4; mt++)
#pragma unroll
                for (int nt = 0; nt < 2; nt++)
                    MMA16816(acc[mt][nt], Afh[mt], Bf[nt * 2], Bf[nt * 2 + 1]);
        }
        __syncthreads();
    }

    // epilogue: weighted atomic accumulate onto residual out
    int g = lane >> 2, tg = lane & 3;
#pragma unroll
    for (int mt = 0; mt < 4; mt++) {
        int mA = m0 + 64 * wm + 16 * mt + g;
        int mB = mA + 8;
        float wA = (mA < cnt) ? g_wt[e][mA] : 0.f;
        float wB = (mB < cnt) ? g_wt[e][mB] : 0.f;
        int tokA = (mA < cnt) ? g_tok[e][mA] : 0;
        int tokB = (mB < cnt) ? g_tok[e][mB] : 0;
#pragma unroll
        for (int nt = 0; nt < 2; nt++) {
            int n = n0 + 16 * wn + 8 * nt + 2 * tg;
            float2 bb = *(const float2*)&b2[(size_t)e * HIDDEN + n];
            if (mA < cnt) {
                float* op = out + (size_t)tokA * HIDDEN + n;
                atomicAdd(op,     (acc[mt][nt][0] + bb.x) * wA);
                atomicAdd(op + 1, (acc[mt][nt][1] + bb.y) * wA);
            }
            if (mB < cnt) {
                float* op = out + (size_t)tokB * HIDDEN + n;
                atomicAdd(op,     (acc[mt][nt][2] + bb.x) * wB);
                atomicAdd(op + 1, (acc[mt][nt][3] + bb.y) * wB);
            }
        }
    }
}

// ---------------- launch ----------------
extern "C" void kernel_launch(void* const* d_in, const int* in_sizes, int n_in,
                              void* d_out, int out_size) {
    const float* hidden   = (const float*)d_in[0];
    const float* w_router = (const float*)d_in[1];
    const float* b_router = (const float*)d_in[2];
    const float* w1       = (const float*)d_in[3];
    const float* b1       = (const float*)d_in[4];
    const float* w2       = (const float*)d_in[5];
    const float* b2       = (const float*)d_in[6];
    float* out = (float*)d_out;

    const int SMEM = 2 * G_STAGE + 1024;  // 99328
    cudaFuncSetAttribute(gemm1_mma, cudaFuncAttributeMaxDynamicSharedMemorySize, SMEM);
    cudaFuncSetAttribute(gemm2_mma, cudaFuncAttributeMaxDynamicSharedMemorySize, SMEM);

    // ---- fork: weight transposes on side streams ----
    cudaEventRecord(g_fj.evRoot, 0);
    cudaStreamWaitEvent(g_fj.s1, g_fj.evRoot, 0);
    cudaStreamWaitEvent(g_fj.s2, g_fj.evRoot, 0);
    transpose_split_kernel<<<dim3(INTER / 32, HIDDEN / 64, NUM_EXPERTS), dim3(32, 8), 0, g_fj.s1>>>(
        w1, 0, HIDDEN, INTER);
    cudaEventRecord(g_fj.evW1, g_fj.s1);
    transpose_split_kernel<<<dim3(HIDDEN / 32, INTER / 64, NUM_EXPERTS), dim3(32, 8), 0, g_fj.s2>>>(
        w2, 1, INTER, HIDDEN);
    cudaEventRecord(g_fj.evW2, g_fj.s2);

    // ---- main stream: residual init + router(+split) + loss ----
    cudaMemcpyAsync(out, hidden, (size_t)NTOK * HIDDEN * sizeof(float),
                    cudaMemcpyDeviceToDevice);
    reset_kernel<<<1, 32>>>();
    router_kernel<<<NTOK / 8, 256>>>(hidden, w_router, b_router);
    int write_loss = (out_size > NTOK * HIDDEN) ? 1 : 0;
    loss_kernel<<<1, 256>>>(out, write_loss);

    // ---- join w1t, run gemm1; join w2t, run gemm2 ----
    cudaStreamWaitEvent(0, g_fj.evW1, 0);
    gemm1_mma<<<dim3(INTER / 64, MAXROWS / 128, NUM_EXPERTS), 256, SMEM>>>(b1);
    cudaStreamWaitEvent(0, g_fj.evW2, 0);
    gemm2_mma<<<dim3(HIDDEN / 64, MAXROWS / 128, NUM_EXPERTS), 256, SMEM>>>(b2, out);
}

// round 13
// speedup vs baseline: 4.3635x; 1.0319x over previous
#include <cuda_runtime.h>
#include <cuda_bf16.h>
#include <math.h>

// Problem constants
#define NUM_EXPERTS 8
#define TOP_K 2
#define HIDDEN 512
#define INTER 2048
#define NTOK 2048
#define NSLOT (NTOK * TOP_K)
#define MAXROWS 2048

#define BKC 64            // k per chunk (128 B bf16 rows)
#define G_STAGE 49152     // per-stage smem: A hi/lo 32K + B hi/lo 16K

// ---------------- device scratch ----------------
__device__ int   g_cnt[NUM_EXPERTS];
__device__ int   g_tok[NUM_EXPERTS][MAXROWS];
__device__ float g_wt[NUM_EXPERTS][MAXROWS];
__device__ float g_probs[NTOK * NUM_EXPERTS];
__device__ __nv_bfloat16 g_xh[(size_t)NTOK * HIDDEN];
__device__ __nv_bfloat16 g_xl[(size_t)NTOK * HIDDEN];
__device__ __nv_bfloat16 g_hmid_hi[(size_t)NUM_EXPERTS * MAXROWS * INTER];
__device__ __nv_bfloat16 g_hmid_lo[(size_t)NUM_EXPERTS * MAXROWS * INTER];
__device__ __nv_bfloat16 g_w1t_hi[(size_t)NUM_EXPERTS * INTER * HIDDEN];
__device__ __nv_bfloat16 g_w1t_lo[(size_t)NUM_EXPERTS * INTER * HIDDEN];
__device__ __nv_bfloat16 g_w2t_hi[(size_t)NUM_EXPERTS * HIDDEN * INTER];
__device__ __nv_bfloat16 g_w2t_lo[(size_t)NUM_EXPERTS * HIDDEN * INTER];

// ---------------- host-side streams/events (static init, pre-checkpoint) ----
struct ForkJoin {
    cudaStream_t s1, s2;
    cudaEvent_t evRoot, evW1, evW2, evR, evLoss;
    ForkJoin() {
        cudaStreamCreateWithFlags(&s1, cudaStreamNonBlocking);
        cudaStreamCreateWithFlags(&s2, cudaStreamNonBlocking);
        cudaEventCreateWithFlags(&evRoot, cudaEventDisableTiming);
        cudaEventCreateWithFlags(&evW1, cudaEventDisableTiming);
        cudaEventCreateWithFlags(&evW2, cudaEventDisableTiming);
        cudaEventCreateWithFlags(&evR, cudaEventDisableTiming);
        cudaEventCreateWithFlags(&evLoss, cudaEventDisableTiming);
    }
};
static ForkJoin g_fj;

// ---------------- helpers ----------------
__device__ __forceinline__ unsigned smem_u32(const void* p) {
    unsigned a;
    asm("{ .reg .u64 t; cvta.to.shared.u64 t, %1; cvt.u32.u64 %0, t; }"
        : "=r"(a) : "l"(p));
    return a;
}
__device__ __forceinline__ unsigned sw128(unsigned off) {
    return off ^ ((off >> 3) & 0x70);
}
__device__ __forceinline__ unsigned pack2_hi(float a, float b,
                                             __nv_bfloat16& ha, __nv_bfloat16& hb) {
    ha = __float2bfloat16(a);
    hb = __float2bfloat16(b);
    return (unsigned)__bfloat16_as_ushort(ha) | ((unsigned)__bfloat16_as_ushort(hb) << 16);
}
__device__ __forceinline__ float gelu_tanh(float x) {
    const float c = 0.7978845608028654f;
    float x3 = x * x * x;
    return 0.5f * x * (1.0f + tanhf(c * (x + 0.044715f * x3)));
}

#define CP16(dst, src, nbytes) \
    asm volatile("cp.async.cg.shared.global [%0], [%1], 16, %2;" \
        :: "r"(dst), "l"(src), "r"((unsigned)(nbytes)) : "memory")
#define CP_COMMIT() asm volatile("cp.async.commit_group;" ::: "memory")
#define CP_WAIT0()  asm volatile("cp.async.wait_group 0;" ::: "memory")

#define LDSM4(r, addr) \
    asm volatile("ldmatrix.sync.aligned.m8n8.x4.shared.b16 {%0,%1,%2,%3}, [%4];" \
        : "=r"((r)[0]), "=r"((r)[1]), "=r"((r)[2]), "=r"((r)[3]) : "r"(addr))

#define MMA16816(c, a, b0v, b1v) \
    asm volatile("mma.sync.aligned.m16n8k16.row.col.f32.bf16.bf16.f32 " \
        "{%0,%1,%2,%3}, {%4,%5,%6,%7}, {%8,%9}, {%0,%1,%2,%3};" \
        : "+f"((c)[0]), "+f"((c)[1]), "+f"((c)[2]), "+f"((c)[3]) \
        : "r"((a)[0]), "r"((a)[1]), "r"((a)[2]), "r"((a)[3]), "r"(b0v), "r"(b1v))

// ---------------- kernel 0: reset ----------------
__global__ void reset_kernel() {
    int t = threadIdx.x;
    if (t < NUM_EXPERTS) g_cnt[t] = 0;
}

// ---------------- kernel 1: router (+ fused activation split) ----------------
// 64 blocks x 1024 threads; 32 tokens per block (one warp each).
__global__ void __launch_bounds__(1024)
router_kernel(const float* __restrict__ hidden,
              const float* __restrict__ w_router,
              const float* __restrict__ b_router) {
    __shared__ float wsm[NUM_EXPERTS][HIDDEN];
    int tid = threadIdx.x;

    // fused split: this block owns tokens [blockIdx.x*32, +32) = 16384 floats
    {
        size_t base = (size_t)blockIdx.x * 32 * HIDDEN;
#pragma unroll
        for (int u = 0; u < 4; u++) {
            size_t idx = base + ((size_t)(tid + u * 1024)) * 4;
            float4 v = *(const float4*)&hidden[idx];
            __nv_bfloat16 h0, h1, h2, h3, d0, d1, d2, d3;
            unsigned hp0 = pack2_hi(v.x, v.y, h0, h1);
            unsigned hp1 = pack2_hi(v.z, v.w, h2, h3);
            unsigned lp0 = pack2_hi(v.x - __bfloat162float(h0), v.y - __bfloat162float(h1), d0, d1);
            unsigned lp1 = pack2_hi(v.z - __bfloat162float(h2), v.w - __bfloat162float(h3), d2, d3);
            *(uint2*)&g_xh[idx] = make_uint2(hp0, hp1);
            *(uint2*)&g_xl[idx] = make_uint2(lp0, lp1);
        }
    }

    for (int i = tid; i < NUM_EXPERTS * HIDDEN; i += 1024) {
        int e = i / HIDDEN, h = i % HIDDEN;
        wsm[e][h] = w_router[h * NUM_EXPERTS + e];
    }
    __syncthreads();

    int warp = tid >> 5, lane = tid & 31;
    int t = blockIdx.x * 32 + warp;

    const float* x = hidden + (size_t)t * HIDDEN;
    float acc[NUM_EXPERTS];
#pragma unroll
    for (int e = 0; e < NUM_EXPERTS; e++) acc[e] = 0.f;
    for (int i = lane; i < HIDDEN; i += 32) {
        float xv = x[i];
#pragma unroll
        for (int e = 0; e < NUM_EXPERTS; e++) acc[e] += xv * wsm[e][i];
    }
#pragma unroll
    for (int off = 16; off > 0; off >>= 1) {
#pragma unroll
        for (int e = 0; e < NUM_EXPERTS; e++)
            acc[e] += __shfl_xor_sync(0xffffffffu, acc[e], off);
    }
    if (lane == 0) {
        float logits[NUM_EXPERTS], mx = -1e30f;
#pragma unroll
        for (int e = 0; e < NUM_EXPERTS; e++) {
            logits[e] = acc[e] + b_router[e];
            mx = fmaxf(mx, logits[e]);
        }
        float p[NUM_EXPERTS], Z = 0.f;
#pragma unroll
        for (int e = 0; e < NUM_EXPERTS; e++) { p[e] = __expf(logits[e] - mx); Z += p[e]; }
        float invZ = 1.0f / Z;
#pragma unroll
        for (int e = 0; e < NUM_EXPERTS; e++) {
            p[e] *= invZ;
            g_probs[t * NUM_EXPERTS + e] = p[e];
        }
        int i1 = 0; float p1 = p[0];
#pragma unroll
        for (int e = 1; e < NUM_EXPERTS; e++) if (p[e] > p1) { p1 = p[e]; i1 = e; }
        int i2 = -1; float p2 = -1.0f;
#pragma unroll
        for (int e = 0; e < NUM_EXPERTS; e++)
            if (e != i1 && p[e] > p2) { p2 = p[e]; i2 = e; }
        float rs = 1.0f / (p1 + p2);
        int pos1 = atomicAdd(&g_cnt[i1], 1);
        g_tok[i1][pos1] = t; g_wt[i1][pos1] = p1 * rs;
        int pos2 = atomicAdd(&g_cnt[i2], 1);
        g_tok[i2][pos2] = t; g_wt[i2][pos2] = p2 * rs;
    }
}

// ---------------- kernel 2: balance loss (warp-per-expert) ----------------
__global__ void loss_kernel(float* __restrict__ out, int write_loss) {
    __shared__ float part[NUM_EXPERTS];
    int tid = threadIdx.x, wid = tid >> 5, lane = tid & 31;
    if (wid < NUM_EXPERTS) {
        float s = 0.f;
        for (int t = lane; t < NTOK; t += 32)
            s += g_probs[t * NUM_EXPERTS + wid];
#pragma unroll
        for (int off = 16; off > 0; off >>= 1)
            s += __shfl_xor_sync(0xffffffffu, s, off);
        if (lane == 0) part[wid] = s;
    }
    __syncthreads();
    if (tid == 0 && write_loss) {
        float acc = 0.f;
#pragma unroll
        for (int e = 0; e < NUM_EXPERTS; e++) {
            float P = part[e] / (float)NTOK;
            float f = (float)g_cnt[e] / (float)NSLOT;
            acc += f * P;
        }
        out[(size_t)NTOK * HIDDEN] = 0.01f * (float)NUM_EXPERTS * acc;
    }
}

// ---------------- kernel 3: transpose + split weights ----------------
__global__ void transpose_split_kernel(const float* __restrict__ w,
                                       int which, int K, int N) {
    __nv_bfloat16* hi = which ? g_w2t_hi : g_w1t_hi;
    __nv_bfloat16* lo = which ? g_w2t_lo : g_w1t_lo;
    __shared__ float tile[64][33];
    int e = blockIdx.z;
    int n0 = blockIdx.x * 32, k0 = blockIdx.y * 64;
    const float* we = w + (size_t)e * K * N;
    int tx = threadIdx.x, ty = threadIdx.y; // 32 x 8
#pragma unroll
    for (int r = 0; r < 8; r++) {
        int kl = ty + r * 8;
        tile[kl][tx] = we[(size_t)(k0 + kl) * N + n0 + tx];
    }
    __syncthreads();
#pragma unroll
    for (int r = 0; r < 4; r++) {
        int nl = ty + r * 8;
        float v0 = tile[2 * tx][nl];
        float v1 = tile[2 * tx + 1][nl];
        __nv_bfloat16 h0, h1, d0, d1;
        unsigned hp = pack2_hi(v0, v1, h0, h1);
        unsigned lp = pack2_hi(v0 - __bfloat162float(h0), v1 - __bfloat162float(h1), d0, d1);
        size_t o = ((size_t)e * N + n0 + nl) * K + k0 + 2 * tx;
        *(unsigned*)&hi[o] = hp;
        *(unsigned*)&lo[o] = lp;
    }
}

// ======================================================================
// GEMM1: hmid = gelu(gather(x) @ w1 + b1). CTA 128x64, cp.async 2-stage.
// 8 warps (2m x 4n), warp tile 64x16, 3-way bf16 split. 2 CTAs/SM.
// ======================================================================
__global__ void __launch_bounds__(256, 2)
gemm1_mma(const float* __restrict__ b1) {
    int e = blockIdx.z;
    int cnt = g_cnt[e];
    int m0 = blockIdx.y * 128;
    if (m0 >= cnt) return;
    int n0 = blockIdx.x * 64;

    extern __shared__ char dsm[];
    unsigned sb = smem_u32(dsm);
    unsigned base = (sb + 1023u) & ~1023u;

    __shared__ int toks[128];
    int tid = threadIdx.x, wid = tid >> 5, lane = tid & 31;
    if (tid < 128) toks[tid] = (m0 + tid < cnt) ? g_tok[e][m0 + tid] : -1;
    __syncthreads();

    const __nv_bfloat16* w1h = g_w1t_hi + (size_t)e * INTER * HIDDEN;
    const __nv_bfloat16* w1l = g_w1t_lo + (size_t)e * INTER * HIDDEN;

    int wm = wid >> 2, wn = wid & 3;
    int rA = (lane & 7) + 8 * ((lane >> 3) & 1);
    int cA = lane >> 4;
    int rB = (lane & 7) + 8 * (lane >> 4);
    int cB = (lane >> 3) & 1;

    float acc[4][2][4];
#pragma unroll
    for (int i = 0; i < 4; i++)
#pragma unroll
        for (int j = 0; j < 2; j++)
#pragma unroll
            for (int q = 0; q < 4; q++) acc[i][j][q] = 0.f;

    const int KT = HIDDEN / BKC; // 8

    auto issue = [&](int kt, int s) {
        unsigned st = base + s * G_STAGE;
        int k0 = kt * BKC;
#pragma unroll
        for (int u = 0; u < 4; u++) {
            int idx = tid + u * 256;
            int row = idx >> 3, seg = idx & 7;
            unsigned so = sw128((unsigned)(row * 128 + seg * 16));
            int tok = toks[row];
            const __nv_bfloat16* sh = (tok >= 0) ? g_xh + (size_t)tok * HIDDEN + k0 + seg * 8 : g_xh;
            const __nv_bfloat16* sl = (tok >= 0) ? g_xl + (size_t)tok * HIDDEN + k0 + seg * 8 : g_xl;
            unsigned pb = (tok >= 0) ? 16u : 0u;
            CP16(st + so, sh, pb);
            CP16(st + 16384 + so, sl, pb);
        }
#pragma unroll
        for (int u = 0; u < 2; u++) {
            int idx = tid + u * 256;
            int row = idx >> 3, seg = idx & 7;
            unsigned so = sw128((unsigned)(row * 128 + seg * 16));
            size_t bsrc = (size_t)(n0 + row) * HIDDEN + k0 + seg * 8;
            CP16(st + 32768 + so, w1h + bsrc, 16u);
            CP16(st + 40960 + so, w1l + bsrc, 16u);
        }
        CP_COMMIT();
    };

    issue(0, 0);
    for (int kt = 0; kt < KT; kt++) {
        CP_WAIT0();
        __syncthreads();
        if (kt + 1 < KT) issue(kt + 1, (kt + 1) & 1);
        unsigned st = base + (kt & 1) * G_STAGE;
        unsigned uAh = st, uAl = st + 16384, uBh = st + 32768, uBl = st + 40960;
#pragma unroll
        for (int k16 = 0; k16 < 4; k16++) {
            unsigned Afh[4][4], Afl[4][4], Bfh[4], Bfl[4];
#pragma unroll
            for (int mt = 0; mt < 4; mt++) {
                unsigned off = sw128((unsigned)((64 * wm + 16 * mt + rA) * 128 + (2 * k16 + cA) * 16));
                LDSM4(Afh[mt], uAh + off);
                LDSM4(Afl[mt], uAl + off);
            }
            {
                unsigned off = sw128((unsigned)((16 * wn + rB) * 128 + (2 * k16 + cB) * 16));
                LDSM4(Bfh, uBh + off);
                LDSM4(Bfl, uBl + off);
            }
#pragma unroll
            for (int mt = 0; mt < 4; mt++)
#pragma unroll
                for (int nt = 0; nt < 2; nt++)
                    MMA16816(acc[mt][nt], Afh[mt], Bfh[nt * 2], Bfh[nt * 2 + 1]);
#pragma unroll
            for (int mt = 0; mt < 4; mt++)
#pragma unroll
                for (int nt = 0; nt < 2; nt++)
                    MMA16816(acc[mt][nt], Afl[mt], Bfh[nt * 2], Bfh[nt * 2 + 1]);
#pragma unroll
            for (int mt = 0; mt < 4; mt++)
#pragma unroll
                for (int nt = 0; nt < 2; nt++)
                    MMA16816(acc[mt][nt], Afh[mt], Bfl[nt * 2], Bfl[nt * 2 + 1]);
        }
        __syncthreads();
    }

    // epilogue: bias + gelu, split, write hmid hi/lo planes
    int g = lane >> 2, tg = lane & 3;
#pragma unroll
    for (int mt = 0; mt < 4; mt++) {
        int mA = m0 + 64 * wm + 16 * mt + g;
        int mB = mA + 8;
#pragma unroll
        for (int nt = 0; nt < 2; nt++) {
            int n = n0 + 16 * wn + 8 * nt + 2 * tg;
            float2 bb = *(const float2*)&b1[(size_t)e * INTER + n];
            if (mA < cnt) {
                float v0 = gelu_tanh(acc[mt][nt][0] + bb.x);
                float v1 = gelu_tanh(acc[mt][nt][1] + bb.y);
                __nv_bfloat16 h0, h1, d0, d1;
                unsigned hp = pack2_hi(v0, v1, h0, h1);
                unsigned lp = pack2_hi(v0 - __bfloat162float(h0), v1 - __bfloat162float(h1), d0, d1);
                size_t o = ((size_t)e * MAXROWS + mA) * INTER + n;
                *(unsigned*)&g_hmid_hi[o] = hp;
                *(unsigned*)&g_hmid_lo[o] = lp;
            }
            if (mB < cnt) {
                float v2 = gelu_tanh(acc[mt][nt][2] + bb.x);
                float v3 = gelu_tanh(acc[mt][nt][3] + bb.y);
                __nv_bfloat16 h2, h3, d2, d3;
                unsigned hp = pack2_hi(v2, v3, h2, h3);
                unsigned lp = pack2_hi(v2 - __bfloat162float(h2), v3 - __bfloat162float(h3), d2, d3);
                size_t o = ((size_t)e * MAXROWS + mB) * INTER + n;
                *(unsigned*)&g_hmid_hi[o] = hp;
                *(unsigned*)&g_hmid_lo[o] = lp;
            }
        }
    }
}

// ======================================================================
// GEMM2: out[tok] += wt*(hmid @ w2 + b2). CTA 128x64, cp.async 2-stage.
// ======================================================================
__global__ void __launch_bounds__(256, 2)
gemm2_mma(const float* __restrict__ b2, float* __restrict__ out) {
    int e = blockIdx.z;
    int cnt = g_cnt[e];
    int m0 = blockIdx.y * 128;
    if (m0 >= cnt) return;
    int n0 = blockIdx.x * 64;

    extern __shared__ char dsm[];
    unsigned sb = smem_u32(dsm);
    unsigned base = (sb + 1023u) & ~1023u;

    int tid = threadIdx.x, wid = tid >> 5, lane = tid & 31;
    int wm = wid >> 2, wn = wid & 3;
    int rA = (lane & 7) + 8 * ((lane >> 3) & 1);
    int cA = lane >> 4;
    int rB = (lane & 7) + 8 * (lane >> 4);
    int cB = (lane >> 3) & 1;

    const __nv_bfloat16* w2h = g_w2t_hi + (size_t)e * HIDDEN * INTER;
    const __nv_bfloat16* w2l = g_w2t_lo + (size_t)e * HIDDEN * INTER;
    const __nv_bfloat16* ah = g_hmid_hi + (size_t)e * MAXROWS * INTER;
    const __nv_bfloat16* al = g_hmid_lo + (size_t)e * MAXROWS * INTER;

    float acc[4][2][4];
#pragma unroll
    for (int i = 0; i < 4; i++)
#pragma unroll
        for (int j = 0; j < 2; j++)
#pragma unroll
            for (int q = 0; q < 4; q++) acc[i][j][q] = 0.f;

    const int KT = INTER / BKC; // 32

    auto issue = [&](int kt, int s) {
        unsigned st = base + s * G_STAGE;
        int k0 = kt * BKC;
#pragma unroll
        for (int u = 0; u < 4; u++) {
            int idx = tid + u * 256;
            int row = idx >> 3, seg = idx & 7;
            unsigned so = sw128((unsigned)(row * 128 + seg * 16));
            int gm = m0 + row;
            size_t asrc = (size_t)gm * INTER + k0 + seg * 8;
            unsigned pb = (gm < cnt) ? 16u : 0u;
            const __nv_bfloat16* sh = (gm < cnt) ? ah + asrc : ah;
            const __nv_bfloat16* sl = (gm < cnt) ? al + asrc : al;
            CP16(st + so, sh, pb);
            CP16(st + 16384 + so, sl, pb);
        }
#pragma unroll
        for (int u = 0; u < 2; u++) {
            int idx = tid + u * 256;
            int row = idx >> 3, seg = idx & 7;
            unsigned so = sw128((unsigned)(row * 128 + seg * 16));
            size_t bsrc = (size_t)(n0 + row) * INTER + k0 + seg * 8;
            CP16(st + 32768 + so, w2h + bsrc, 16u);
            CP16(st + 40960 + so, w2l + bsrc, 16u);
        }
        CP_COMMIT();
    };

    issue(0, 0);
    for (int kt = 0; kt < KT; kt++) {
        CP_WAIT0();
        __syncthreads();
        if (kt + 1 < KT) issue(kt + 1, (kt + 1) & 1);
        unsigned st = base + (kt & 1) * G_STAGE;
        unsigned uAh = st, uAl = st + 16384, uBh = st + 32768, uBl = st + 40960;
#pragma unroll
        for (int k16 = 0; k16 < 4; k16++) {
            unsigned Afh[4][4], Afl[4][4], Bfh[4], Bfl[4];
#pragma unroll
            for (int mt = 0; mt < 4; mt++) {
                unsigned off = sw128((unsigned)((64 * wm + 16 * mt + rA) * 128 + (2 * k16 + cA) * 16));
                LDSM4(Afh[mt], uAh + off);
                LDSM4(Afl[mt], uAl + off);
            }
            {
                unsigned off = sw128((unsigned)((16 * wn + rB) * 128 + (2 * k16 + cB) * 16));
                LDSM4(Bfh, uBh + off);
                LDSM4(Bfl, uBl + off);
            }
#pragma unroll
            for (int mt = 0; mt < 4; mt++)
#pragma unroll
                for (int nt = 0; nt < 2; nt++)
                    MMA16816(acc[mt][nt], Afh[mt], Bfh[nt * 2], Bfh[nt * 2 + 1]);
#pragma unroll
            for (int mt = 0; mt < 4; mt++)
#pragma unroll
                for (int nt = 0; nt < 2; nt++)
                    MMA16816(acc[mt][nt], Afl[mt], Bfh[nt * 2], Bfh[nt * 2 + 1]);
#pragma unroll
            for (int mt = 0; mt < 4; mt++)
#pragma unroll
                for (int nt = 0; nt < 2; nt++)
                    MMA16816(acc[mt][nt], Afh[mt], Bfl[nt * 2], Bfl[nt * 2 + 1]);
        }
        __syncthreads();
    }

    // epilogue: weighted atomic accumulate onto residual out
    int g = lane >> 2, tg = lane & 3;
#pragma unroll
    for (int mt = 0; mt < 4; mt++) {
        int mA = m0 + 64 * wm + 16 * mt + g;
        int mB = mA + 8;
        float wA = (mA < cnt) ? g_wt[e][mA] : 0.f;
        float wB = (mB < cnt) ? g_wt[e][mB] : 0.f;
        int tokA = (mA < cnt) ? g_tok[e][mA] : 0;
        int tokB = (mB < cnt) ? g_tok[e][mB] : 0;
#pragma unroll
        for (int nt = 0; nt < 2; nt++) {
            int n = n0 + 16 * wn + 8 * nt + 2 * tg;
            float2 bb = *(const float2*)&b2[(size_t)e * HIDDEN + n];
            if (mA < cnt) {
                float* op = out + (size_t)tokA * HIDDEN + n;
                atomicAdd(op,     (acc[mt][nt][0] + bb.x) * wA);
                atomicAdd(op + 1, (acc[mt][nt][1] + bb.y) * wA);
            }
            if (mB < cnt) {
                float* op = out + (size_t)tokB * HIDDEN + n;
                atomicAdd(op,     (acc[mt][nt][2] + bb.x) * wB);
                atomicAdd(op + 1, (acc[mt][nt][3] + bb.y) * wB);
            }
        }
    }
}

// ---------------- launch ----------------
extern "C" void kernel_launch(void* const* d_in, const int* in_sizes, int n_in,
                              void* d_out, int out_size) {
    const float* hidden   = (const float*)d_in[0];
    const float* w_router = (const float*)d_in[1];
    const float* b_router = (const float*)d_in[2];
    const float* w1       = (const float*)d_in[3];
    const float* b1       = (const float*)d_in[4];
    const float* w2       = (const float*)d_in[5];
    const float* b2       = (const float*)d_in[6];
    float* out = (float*)d_out;

    const int SMEM = 2 * G_STAGE + 1024;  // 99328
    cudaFuncSetAttribute(gemm1_mma, cudaFuncAttributeMaxDynamicSharedMemorySize, SMEM);
    cudaFuncSetAttribute(gemm2_mma, cudaFuncAttributeMaxDynamicSharedMemorySize, SMEM);

    // ---- fork: weight transposes on side streams ----
    cudaEventRecord(g_fj.evRoot, 0);
    cudaStreamWaitEvent(g_fj.s1, g_fj.evRoot, 0);
    cudaStreamWaitEvent(g_fj.s2, g_fj.evRoot, 0);
    transpose_split_kernel<<<dim3(INTER / 32, HIDDEN / 64, NUM_EXPERTS), dim3(32, 8), 0, g_fj.s1>>>(
        w1, 0, HIDDEN, INTER);
    cudaEventRecord(g_fj.evW1, g_fj.s1);
    transpose_split_kernel<<<dim3(HIDDEN / 32, INTER / 64, NUM_EXPERTS), dim3(32, 8), 0, g_fj.s2>>>(
        w2, 1, INTER, HIDDEN);
    cudaEventRecord(g_fj.evW2, g_fj.s2);

    // ---- main stream: residual init + router(+split) ----
    cudaMemcpyAsync(out, hidden, (size_t)NTOK * HIDDEN * sizeof(float),
                    cudaMemcpyDeviceToDevice);
    reset_kernel<<<1, 32>>>();
    router_kernel<<<NTOK / 32, 1024>>>(hidden, w_router, b_router);
    cudaEventRecord(g_fj.evR, 0);

    // ---- loss overlapped with gemm1 on s1 (after w1 transpose + router) ----
    cudaStreamWaitEvent(g_fj.s1, g_fj.evR, 0);
    int write_loss = (out_size > NTOK * HIDDEN) ? 1 : 0;
    loss_kernel<<<1, 256, 0, g_fj.s1>>>(out, write_loss);
    cudaEventRecord(g_fj.evLoss, g_fj.s1);

    // ---- join w1t, run gemm1; join w2t, run gemm2; join loss ----
    cudaStreamWaitEvent(0, g_fj.evW1, 0);
    gemm1_mma<<<dim3(INTER / 64, MAXROWS / 128, NUM_EXPERTS), 256, SMEM>>>(b1);
    cudaStreamWaitEvent(0, g_fj.evW2, 0);
    gemm2_mma<<<dim3(HIDDEN / 64, MAXROWS / 128, NUM_EXPERTS), 256, SMEM>>>(b2, out);
    cudaStreamWaitEvent(0, g_fj.evLoss, 0);
}

// round 14
// speedup vs baseline: 4.4104x; 1.0107x over previous
#include <cuda_runtime.h>
#include <cuda_bf16.h>
#include <math.h>

// Problem constants
#define NUM_EXPERTS 8
#define TOP_K 2
#define HIDDEN 512
#define INTER 2048
#define NTOK 2048
#define NSLOT (NTOK * TOP_K)
#define MAXROWS 2048

#define BKC 64            // k per chunk (128 B bf16 rows)
#define G_STAGE 49152     // per-stage smem: A hi/lo 32K + B hi/lo 16K

// ---------------- device scratch ----------------
__device__ int   g_cnt[NUM_EXPERTS];
__device__ int   g_tok[NUM_EXPERTS][MAXROWS];
__device__ float g_wt[NUM_EXPERTS][MAXROWS];
__device__ float g_probs[NTOK * NUM_EXPERTS];
__device__ __nv_bfloat16 g_xh[(size_t)NTOK * HIDDEN];
__device__ __nv_bfloat16 g_xl[(size_t)NTOK * HIDDEN];
__device__ __nv_bfloat16 g_hmid_hi[(size_t)NUM_EXPERTS * MAXROWS * INTER];
__device__ __nv_bfloat16 g_hmid_lo[(size_t)NUM_EXPERTS * MAXROWS * INTER];
__device__ __nv_bfloat16 g_w1t_hi[(size_t)NUM_EXPERTS * INTER * HIDDEN];
__device__ __nv_bfloat16 g_w1t_lo[(size_t)NUM_EXPERTS * INTER * HIDDEN];
__device__ __nv_bfloat16 g_w2t_hi[(size_t)NUM_EXPERTS * HIDDEN * INTER];
__device__ __nv_bfloat16 g_w2t_lo[(size_t)NUM_EXPERTS * HIDDEN * INTER];

// ---------------- host-side streams/events (static init, pre-checkpoint) ----
struct ForkJoin {
    cudaStream_t s1, s2;
    cudaEvent_t evRoot, evW1, evX, evW2M, evR, evLoss, evG1a, evG2a;
    ForkJoin() {
        cudaStreamCreateWithFlags(&s1, cudaStreamNonBlocking);
        cudaStreamCreateWithFlags(&s2, cudaStreamNonBlocking);
        cudaEventCreateWithFlags(&evRoot, cudaEventDisableTiming);
        cudaEventCreateWithFlags(&evW1, cudaEventDisableTiming);
        cudaEventCreateWithFlags(&evX, cudaEventDisableTiming);
        cudaEventCreateWithFlags(&evW2M, cudaEventDisableTiming);
        cudaEventCreateWithFlags(&evR, cudaEventDisableTiming);
        cudaEventCreateWithFlags(&evLoss, cudaEventDisableTiming);
        cudaEventCreateWithFlags(&evG1a, cudaEventDisableTiming);
        cudaEventCreateWithFlags(&evG2a, cudaEventDisableTiming);
    }
};
static ForkJoin g_fj;

// ---------------- helpers ----------------
__device__ __forceinline__ unsigned smem_u32(const void* p) {
    unsigned a;
    asm("{ .reg .u64 t; cvta.to.shared.u64 t, %1; cvt.u32.u64 %0, t; }"
        : "=r"(a) : "l"(p));
    return a;
}
__device__ __forceinline__ unsigned sw128(unsigned off) {
    return off ^ ((off >> 3) & 0x70);
}
__device__ __forceinline__ unsigned pack2_hi(float a, float b,
                                             __nv_bfloat16& ha, __nv_bfloat16& hb) {
    ha = __float2bfloat16(a);
    hb = __float2bfloat16(b);
    return (unsigned)__bfloat16_as_ushort(ha) | ((unsigned)__bfloat16_as_ushort(hb) << 16);
}
__device__ __forceinline__ float gelu_tanh(float x) {
    const float c = 0.7978845608028654f;
    float x3 = x * x * x;
    return 0.5f * x * (1.0f + tanhf(c * (x + 0.044715f * x3)));
}

#define CP16(dst, src, nbytes) \
    asm volatile("cp.async.cg.shared.global [%0], [%1], 16, %2;" \
        :: "r"(dst), "l"(src), "r"((unsigned)(nbytes)) : "memory")
#define CP_COMMIT() asm volatile("cp.async.commit_group;" ::: "memory")
#define CP_WAIT0()  asm volatile("cp.async.wait_group 0;" ::: "memory")

#define LDSM4(r, addr) \
    asm volatile("ldmatrix.sync.aligned.m8n8.x4.shared.b16 {%0,%1,%2,%3}, [%4];" \
        : "=r"((r)[0]), "=r"((r)[1]), "=r"((r)[2]), "=r"((r)[3]) : "r"(addr))

#define MMA16816(c, a, b0v, b1v) \
    asm volatile("mma.sync.aligned.m16n8k16.row.col.f32.bf16.bf16.f32 " \
        "{%0,%1,%2,%3}, {%4,%5,%6,%7}, {%8,%9}, {%0,%1,%2,%3};" \
        : "+f"((c)[0]), "+f"((c)[1]), "+f"((c)[2]), "+f"((c)[3]) \
        : "r"((a)[0]), "r"((a)[1]), "r"((a)[2]), "r"((a)[3]), "r"(b0v), "r"(b1v))

// ---------------- kernel 0: reset ----------------
__global__ void reset_kernel() {
    int t = threadIdx.x;
    if (t < NUM_EXPERTS) g_cnt[t] = 0;
}

// ---------------- kernel: split activations (side stream) ----------------
__global__ void split_x_kernel(const float* __restrict__ hidden) {
    int i = blockIdx.x * 256 + threadIdx.x;  // one float4 per thread
    float4 v = *(const float4*)&hidden[(size_t)i * 4];
    __nv_bfloat16 h0, h1, h2, h3, d0, d1, d2, d3;
    unsigned hp0 = pack2_hi(v.x, v.y, h0, h1);
    unsigned hp1 = pack2_hi(v.z, v.w, h2, h3);
    unsigned lp0 = pack2_hi(v.x - __bfloat162float(h0), v.y - __bfloat162float(h1), d0, d1);
    unsigned lp1 = pack2_hi(v.z - __bfloat162float(h2), v.w - __bfloat162float(h3), d2, d3);
    *(uint2*)&g_xh[(size_t)i * 4] = make_uint2(hp0, hp1);
    *(uint2*)&g_xl[(size_t)i * 4] = make_uint2(lp0, lp1);
}

// ---------------- kernel 1: router ----------------
// 256 blocks x 256 threads; one warp per token; float4 dot products.
__global__ void __launch_bounds__(256)
router_kernel(const float* __restrict__ hidden,
              const float* __restrict__ w_router,
              const float* __restrict__ b_router) {
    __shared__ float wsm[NUM_EXPERTS][HIDDEN];
    int tid = threadIdx.x;
    for (int i = tid; i < NUM_EXPERTS * HIDDEN; i += 256) {
        int e = i / HIDDEN, h = i % HIDDEN;
        wsm[e][h] = w_router[h * NUM_EXPERTS + e];
    }
    __syncthreads();

    int warp = tid >> 5, lane = tid & 31;
    int t = blockIdx.x * 8 + warp;

    const float* x = hidden + (size_t)t * HIDDEN;
    float acc[NUM_EXPERTS];
#pragma unroll
    for (int e = 0; e < NUM_EXPERTS; e++) acc[e] = 0.f;
#pragma unroll
    for (int it = 0; it < HIDDEN / 128; it++) {
        int h = it * 128 + lane * 4;
        float4 v = *(const float4*)&x[h];
#pragma unroll
        for (int e = 0; e < NUM_EXPERTS; e++) {
            float4 w = *(const float4*)&wsm[e][h];
            acc[e] += v.x * w.x + v.y * w.y + v.z * w.z + v.w * w.w;
        }
    }
#pragma unroll
    for (int off = 16; off > 0; off >>= 1) {
#pragma unroll
        for (int e = 0; e < NUM_EXPERTS; e++)
            acc[e] += __shfl_xor_sync(0xffffffffu, acc[e], off);
    }
    if (lane == 0) {
        float logits[NUM_EXPERTS], mx = -1e30f;
#pragma unroll
        for (int e = 0; e < NUM_EXPERTS; e++) {
            logits[e] = acc[e] + b_router[e];
            mx = fmaxf(mx, logits[e]);
        }
        float p[NUM_EXPERTS], Z = 0.f;
#pragma unroll
        for (int e = 0; e < NUM_EXPERTS; e++) { p[e] = __expf(logits[e] - mx); Z += p[e]; }
        float invZ = 1.0f / Z;
#pragma unroll
        for (int e = 0; e < NUM_EXPERTS; e++) {
            p[e] *= invZ;
            g_probs[t * NUM_EXPERTS + e] = p[e];
        }
        int i1 = 0; float p1 = p[0];
#pragma unroll
        for (int e = 1; e < NUM_EXPERTS; e++) if (p[e] > p1) { p1 = p[e]; i1 = e; }
        int i2 = -1; float p2 = -1.0f;
#pragma unroll
        for (int e = 0; e < NUM_EXPERTS; e++)
            if (e != i1 && p[e] > p2) { p2 = p[e]; i2 = e; }
        float rs = 1.0f / (p1 + p2);
        int pos1 = atomicAdd(&g_cnt[i1], 1);
        g_tok[i1][pos1] = t; g_wt[i1][pos1] = p1 * rs;
        int pos2 = atomicAdd(&g_cnt[i2], 1);
        g_tok[i2][pos2] = t; g_wt[i2][pos2] = p2 * rs;
    }
}

// ---------------- kernel 2: balance loss (warp-per-expert) ----------------
__global__ void loss_kernel(float* __restrict__ out, int write_loss) {
    __shared__ float part[NUM_EXPERTS];
    int tid = threadIdx.x, wid = tid >> 5, lane = tid & 31;
    if (wid < NUM_EXPERTS) {
        float s = 0.f;
        for (int t = lane; t < NTOK; t += 32)
            s += g_probs[t * NUM_EXPERTS + wid];
#pragma unroll
        for (int off = 16; off > 0; off >>= 1)
            s += __shfl_xor_sync(0xffffffffu, s, off);
        if (lane == 0) part[wid] = s;
    }
    __syncthreads();
    if (tid == 0 && write_loss) {
        float acc = 0.f;
#pragma unroll
        for (int e = 0; e < NUM_EXPERTS; e++) {
            float P = part[e] / (float)NTOK;
            float f = (float)g_cnt[e] / (float)NSLOT;
            acc += f * P;
        }
        out[(size_t)NTOK * HIDDEN] = 0.01f * (float)NUM_EXPERTS * acc;
    }
}

// ---------------- kernel 3: transpose + split weights ----------------
__global__ void transpose_split_kernel(const float* __restrict__ w,
                                       int which, int K, int N) {
    __nv_bfloat16* hi = which ? g_w2t_hi : g_w1t_hi;
    __nv_bfloat16* lo = which ? g_w2t_lo : g_w1t_lo;
    __shared__ float tile[64][33];
    int e = blockIdx.z;
    int n0 = blockIdx.x * 32, k0 = blockIdx.y * 64;
    const float* we = w + (size_t)e * K * N;
    int tx = threadIdx.x, ty = threadIdx.y; // 32 x 8
#pragma unroll
    for (int r = 0; r < 8; r++) {
        int kl = ty + r * 8;
        tile[kl][tx] = we[(size_t)(k0 + kl) * N + n0 + tx];
    }
    __syncthreads();
#pragma unroll
    for (int r = 0; r < 4; r++) {
        int nl = ty + r * 8;
        float v0 = tile[2 * tx][nl];
        float v1 = tile[2 * tx + 1][nl];
        __nv_bfloat16 h0, h1, d0, d1;
        unsigned hp = pack2_hi(v0, v1, h0, h1);
        unsigned lp = pack2_hi(v0 - __bfloat162float(h0), v1 - __bfloat162float(h1), d0, d1);
        size_t o = ((size_t)e * N + n0 + nl) * K + k0 + 2 * tx;
        *(unsigned*)&hi[o] = hp;
        *(unsigned*)&lo[o] = lp;
    }
}

// ======================================================================
// GEMM1: hmid = gelu(gather(x) @ w1 + b1). CTA 128x64, cp.async 2-stage.
// 8 warps (2m x 4n), warp tile 64x16, 3-way bf16 split. 2 CTAs/SM.
// ======================================================================
__global__ void __launch_bounds__(256, 2)
gemm1_mma(const float* __restrict__ b1, int ebase) {
    int e = blockIdx.z + ebase;
    int cnt = g_cnt[e];
    int m0 = blockIdx.y * 128;
    if (m0 >= cnt) return;
    int n0 = blockIdx.x * 64;

    extern __shared__ char dsm[];
    unsigned sb = smem_u32(dsm);
    unsigned base = (sb + 1023u) & ~1023u;

    __shared__ int toks[128];
    int tid = threadIdx.x, wid = tid >> 5, lane = tid & 31;
    if (tid < 128) toks[tid] = (m0 + tid < cnt) ? g_tok[e][m0 + tid] : -1;
    __syncthreads();

    const __nv_bfloat16* w1h = g_w1t_hi + (size_t)e * INTER * HIDDEN;
    const __nv_bfloat16* w1l = g_w1t_lo + (size_t)e * INTER * HIDDEN;

    int wm = wid >> 2, wn = wid & 3;
    int rA = (lane & 7) + 8 * ((lane >> 3) & 1);
    int cA = lane >> 4;
    int rB = (lane & 7) + 8 * (lane >> 4);
    int cB = (lane >> 3) & 1;

    float acc[4][2][4];
#pragma unroll
    for (int i = 0; i < 4; i++)
#pragma unroll
        for (int j = 0; j < 2; j++)
#pragma unroll
            for (int q = 0; q < 4; q++) acc[i][j][q] = 0.f;

    const int KT = HIDDEN / BKC; // 8

    auto issue = [&](int kt, int s) {
        unsigned st = base + s * G_STAGE;
        int k0 = kt * BKC;
#pragma unroll
        for (int u = 0; u < 4; u++) {
            int idx = tid + u * 256;
            int row = idx >> 3, seg = idx & 7;
            unsigned so = sw128((unsigned)(row * 128 + seg * 16));
            int tok = toks[row];
            const __nv_bfloat16* sh = (tok >= 0) ? g_xh + (size_t)tok * HIDDEN + k0 + seg * 8 : g_xh;
            const __nv_bfloat16* sl = (tok >= 0) ? g_xl + (size_t)tok * HIDDEN + k0 + seg * 8 : g_xl;
            unsigned pb = (tok >= 0) ? 16u : 0u;
            CP16(st + so, sh, pb);
            CP16(st + 16384 + so, sl, pb);
        }
#pragma unroll
        for (int u = 0; u < 2; u++) {
            int idx = tid + u * 256;
            int row = idx >> 3, seg = idx & 7;
            unsigned so = sw128((unsigned)(row * 128 + seg * 16));
            size_t bsrc = (size_t)(n0 + row) * HIDDEN + k0 + seg * 8;
            CP16(st + 32768 + so, w1h + bsrc, 16u);
            CP16(st + 40960 + so, w1l + bsrc, 16u);
        }
        CP_COMMIT();
    };

    issue(0, 0);
    for (int kt = 0; kt < KT; kt++) {
        CP_WAIT0();
        __syncthreads();
        if (kt + 1 < KT) issue(kt + 1, (kt + 1) & 1);
        unsigned st = base + (kt & 1) * G_STAGE;
        unsigned uAh = st, uAl = st + 16384, uBh = st + 32768, uBl = st + 40960;
#pragma unroll
        for (int k16 = 0; k16 < 4; k16++) {
            unsigned Afh[4][4], Afl[4][4], Bfh[4], Bfl[4];
#pragma unroll
            for (int mt = 0; mt < 4; mt++) {
                unsigned off = sw128((unsigned)((64 * wm + 16 * mt + rA) * 128 + (2 * k16 + cA) * 16));
                LDSM4(Afh[mt], uAh + off);
                LDSM4(Afl[mt], uAl + off);
            }
            {
                unsigned off = sw128((unsigned)((16 * wn + rB) * 128 + (2 * k16 + cB) * 16));
                LDSM4(Bfh, uBh + off);
                LDSM4(Bfl, uBl + off);
            }
#pragma unroll
            for (int mt = 0; mt < 4; mt++)
#pragma unroll
                for (int nt = 0; nt < 2; nt++)
                    MMA16816(acc[mt][nt], Afh[mt], Bfh[nt * 2], Bfh[nt * 2 + 1]);
#pragma unroll
            for (int mt = 0; mt < 4; mt++)
#pragma unroll
                for (int nt = 0; nt < 2; nt++)
                    MMA16816(acc[mt][nt], Afl[mt], Bfh[nt * 2], Bfh[nt * 2 + 1]);
#pragma unroll
            for (int mt = 0; mt < 4; mt++)
#pragma unroll
                for (int nt = 0; nt < 2; nt++)
                    MMA16816(acc[mt][nt], Afh[mt], Bfl[nt * 2], Bfl[nt * 2 + 1]);
        }
        __syncthreads();
    }

    // epilogue: bias + gelu, split, write hmid hi/lo planes
    int g = lane >> 2, tg = lane & 3;
#pragma unroll
    for (int mt = 0; mt < 4; mt++) {
        int mA = m0 + 64 * wm + 16 * mt + g;
        int mB = mA + 8;
#pragma unroll
        for (int nt = 0; nt < 2; nt++) {
            int n = n0 + 16 * wn + 8 * nt + 2 * tg;
            float2 bb = *(const float2*)&b1[(size_t)e * INTER + n];
            if (mA < cnt) {
                float v0 = gelu_tanh(acc[mt][nt][0] + bb.x);
                float v1 = gelu_tanh(acc[mt][nt][1] + bb.y);
                __nv_bfloat16 h0, h1, d0, d1;
                unsigned hp = pack2_hi(v0, v1, h0, h1);
                unsigned lp = pack2_hi(v0 - __bfloat162float(h0), v1 - __bfloat162float(h1), d0, d1);
                size_t o = ((size_t)e * MAXROWS + mA) * INTER + n;
                *(unsigned*)&g_hmid_hi[o] = hp;
                *(unsigned*)&g_hmid_lo[o] = lp;
            }
            if (mB < cnt) {
                float v2 = gelu_tanh(acc[mt][nt][2] + bb.x);
                float v3 = gelu_tanh(acc[mt][nt][3] + bb.y);
                __nv_bfloat16 h2, h3, d2, d3;
                unsigned hp = pack2_hi(v2, v3, h2, h3);
                unsigned lp = pack2_hi(v2 - __bfloat162float(h2), v3 - __bfloat162float(h3), d2, d3);
                size_t o = ((size_t)e * MAXROWS + mB) * INTER + n;
                *(unsigned*)&g_hmid_hi[o] = hp;
                *(unsigned*)&g_hmid_lo[o] = lp;
            }
        }
    }
}

// ======================================================================
// GEMM2: out[tok] += wt*(hmid @ w2 + b2). CTA 128x64, cp.async 2-stage.
// ======================================================================
__global__ void __launch_bounds__(256, 2)
gemm2_mma(const float* __restrict__ b2, float* __restrict__ out, int ebase) {
    int e = blockIdx.z + ebase;
    int cnt = g_cnt[e];
    int m0 = blockIdx.y * 128;
    if (m0 >= cnt) return;
    int n0 = blockIdx.x * 64;

    extern __shared__ char dsm[];
    unsigned sb = smem_u32(dsm);
    unsigned base = (sb + 1023u) & ~1023u;

    int tid = threadIdx.x, wid = tid >> 5, lane = tid & 31;
    int wm = wid >> 2, wn = wid & 3;
    int rA = (lane & 7) + 8 * ((lane >> 3) & 1);
    int cA = lane >> 4;
    int rB = (lane & 7) + 8 * (lane >> 4);
    int cB = (lane >> 3) & 1;

    const __nv_bfloat16* w2h = g_w2t_hi + (size_t)e * HIDDEN * INTER;
    const __nv_bfloat16* w2l = g_w2t_lo + (size_t)e * HIDDEN * INTER;
    const __nv_bfloat16* ah = g_hmid_hi + (size_t)e * MAXROWS * INTER;
    const __nv_bfloat16* al = g_hmid_lo + (size_t)e * MAXROWS * INTER;

    float acc[4][2][4];
#pragma unroll
    for (int i = 0; i < 4; i++)
#pragma unroll
        for (int j = 0; j < 2; j++)
#pragma unroll
            for (int q = 0; q < 4; q++) acc[i][j][q] = 0.f;

    const int KT = INTER / BKC; // 32

    auto issue = [&](int kt, int s) {
        unsigned st = base + s * G_STAGE;
        int k0 = kt * BKC;
#pragma unroll
        for (int u = 0; u < 4; u++) {
            int idx = tid + u * 256;
            int row = idx >> 3, seg = idx & 7;
            unsigned so = sw128((unsigned)(row * 128 + seg * 16));
            int gm = m0 + row;
            size_t asrc = (size_t)gm * INTER + k0 + seg * 8;
            unsigned pb = (gm < cnt) ? 16u : 0u;
            const __nv_bfloat16* sh = (gm < cnt) ? ah + asrc : ah;
            const __nv_bfloat16* sl = (gm < cnt) ? al + asrc : al;
            CP16(st + so, sh, pb);
            CP16(st + 16384 + so, sl, pb);
        }
#pragma unroll
        for (int u = 0; u < 2; u++) {
            int idx = tid + u * 256;
            int row = idx >> 3, seg = idx & 7;
            unsigned so = sw128((unsigned)(row * 128 + seg * 16));
            size_t bsrc = (size_t)(n0 + row) * INTER + k0 + seg * 8;
            CP16(st + 32768 + so, w2h + bsrc, 16u);
            CP16(st + 40960 + so, w2l + bsrc, 16u);
        }
        CP_COMMIT();
    };

    issue(0, 0);
    for (int kt = 0; kt < KT; kt++) {
        CP_WAIT0();
        __syncthreads();
        if (kt + 1 < KT) issue(kt + 1, (kt + 1) & 1);
        unsigned st = base + (kt & 1) * G_STAGE;
        unsigned uAh = st, uAl = st + 16384, uBh = st + 32768, uBl = st + 40960;
#pragma unroll
        for (int k16 = 0; k16 < 4; k16++) {
            unsigned Afh[4][4], Afl[4][4], Bfh[4], Bfl[4];
#pragma unroll
            for (int mt = 0; mt < 4; mt++) {
                unsigned off = sw128((unsigned)((64 * wm + 16 * mt + rA) * 128 + (2 * k16 + cA) * 16));
                LDSM4(Afh[mt], uAh + off);
                LDSM4(Afl[mt], uAl + off);
            }
            {
                unsigned off = sw128((unsigned)((16 * wn + rB) * 128 + (2 * k16 + cB) * 16));
                LDSM4(Bfh, uBh + off);
                LDSM4(Bfl, uBl + off);
            }
#pragma unroll
            for (int mt = 0; mt < 4; mt++)
#pragma unroll
                for (int nt = 0; nt < 2; nt++)
                    MMA16816(acc[mt][nt], Afh[mt], Bfh[nt * 2], Bfh[nt * 2 + 1]);
#pragma unroll
            for (int mt = 0; mt < 4; mt++)
#pragma unroll
                for (int nt = 0; nt < 2; nt++)
                    MMA16816(acc[mt][nt], Afl[mt], Bfh[nt * 2], Bfh[nt * 2 + 1]);
#pragma unroll
            for (int mt = 0; mt < 4; mt++)
#pragma unroll
                for (int nt = 0; nt < 2; nt++)
                    MMA16816(acc[mt][nt], Afh[mt], Bfl[nt * 2], Bfl[nt * 2 + 1]);
        }
        __syncthreads();
    }

    // epilogue: weighted atomic accumulate onto residual out
    int g = lane >> 2, tg = lane & 3;
#pragma unroll
    for (int mt = 0; mt < 4; mt++) {
        int mA = m0 + 64 * wm + 16 * mt + g;
        int mB = mA + 8;
        float wA = (mA < cnt) ? g_wt[e][mA] : 0.f;
        float wB = (mB < cnt) ? g_wt[e][mB] : 0.f;
        int tokA = (mA < cnt) ? g_tok[e][mA] : 0;
        int tokB = (mB < cnt) ? g_tok[e][mB] : 0;
#pragma unroll
        for (int nt = 0; nt < 2; nt++) {
            int n = n0 + 16 * wn + 8 * nt + 2 * tg;
            float2 bb = *(const float2*)&b2[(size_t)e * HIDDEN + n];
            if (mA < cnt) {
                float* op = out + (size_t)tokA * HIDDEN + n;
                atomicAdd(op,     (acc[mt][nt][0] + bb.x) * wA);
                atomicAdd(op + 1, (acc[mt][nt][1] + bb.y) * wA);
            }
            if (mB < cnt) {
                float* op = out + (size_t)tokB * HIDDEN + n;
                atomicAdd(op,     (acc[mt][nt][2] + bb.x) * wB);
                atomicAdd(op + 1, (acc[mt][nt][3] + bb.y) * wB);
            }
        }
    }
}

// ---------------- launch ----------------
extern "C" void kernel_launch(void* const* d_in, const int* in_sizes, int n_in,
                              void* d_out, int out_size) {
    const float* hidden   = (const float*)d_in[0];
    const float* w_router = (const float*)d_in[1];
    const float* b_router = (const float*)d_in[2];
    const float* w1       = (const float*)d_in[3];
    const float* b1       = (const float*)d_in[4];
    const float* w2       = (const float*)d_in[5];
    const float* b2       = (const float*)d_in[6];
    float* out = (float*)d_out;

    const int SMEM = 2 * G_STAGE + 1024;  // 99328
    cudaFuncSetAttribute(gemm1_mma, cudaFuncAttributeMaxDynamicSharedMemorySize, SMEM);
    cudaFuncSetAttribute(gemm2_mma, cudaFuncAttributeMaxDynamicSharedMemorySize, SMEM);

    // ---- fork ----
    cudaEventRecord(g_fj.evRoot, 0);
    cudaStreamWaitEvent(g_fj.s1, g_fj.evRoot, 0);
    cudaStreamWaitEvent(g_fj.s2, g_fj.evRoot, 0);

    // s1: w1 transpose, activation split
    transpose_split_kernel<<<dim3(INTER / 32, HIDDEN / 64, NUM_EXPERTS), dim3(32, 8), 0, g_fj.s1>>>(
        w1, 0, HIDDEN, INTER);
    cudaEventRecord(g_fj.evW1, g_fj.s1);
    split_x_kernel<<<NTOK * HIDDEN / 1024, 256, 0, g_fj.s1>>>(hidden);
    cudaEventRecord(g_fj.evX, g_fj.s1);

    // s2: w2 transpose + residual memcpy
    transpose_split_kernel<<<dim3(HIDDEN / 32, INTER / 64, NUM_EXPERTS), dim3(32, 8), 0, g_fj.s2>>>(
        w2, 1, INTER, HIDDEN);
    cudaMemcpyAsync(out, hidden, (size_t)NTOK * HIDDEN * sizeof(float),
                    cudaMemcpyDeviceToDevice, g_fj.s2);
    cudaEventRecord(g_fj.evW2M, g_fj.s2);

    // main: reset -> router
    reset_kernel<<<1, 32>>>();
    router_kernel<<<NTOK / 8, 256>>>(hidden, w_router, b_router);
    cudaEventRecord(g_fj.evR, 0);

    // loss on s1 (after router); overlaps with gemms
    cudaStreamWaitEvent(g_fj.s1, g_fj.evR, 0);
    int write_loss = (out_size > NTOK * HIDDEN) ? 1 : 0;
    loss_kernel<<<1, 256, 0, g_fj.s1>>>(out, write_loss);
    cudaEventRecord(g_fj.evLoss, g_fj.s1);

    // main: gemm1a (experts 0-3) after w1t + split_x
    cudaStreamWaitEvent(0, g_fj.evW1, 0);
    cudaStreamWaitEvent(0, g_fj.evX, 0);
    gemm1_mma<<<dim3(INTER / 64, MAXROWS / 128, 4), 256, SMEM>>>(b1, 0);
    cudaEventRecord(g_fj.evG1a, 0);
    // main: gemm1b (experts 4-7)
    gemm1_mma<<<dim3(INTER / 64, MAXROWS / 128, 4), 256, SMEM>>>(b1, 4);

    // s2: gemm2a (experts 0-3) after gemm1a (+ w2t/memcpy implicit on s2)
    cudaStreamWaitEvent(g_fj.s2, g_fj.evG1a, 0);
    gemm2_mma<<<dim3(HIDDEN / 64, MAXROWS / 128, 4), 256, SMEM, g_fj.s2>>>(b2, out, 0);
    cudaEventRecord(g_fj.evG2a, g_fj.s2);

    // main: gemm2b (experts 4-7) after gemm1b (implicit) + w2t/memcpy
    cudaStreamWaitEvent(0, g_fj.evW2M, 0);
    gemm2_mma<<<dim3(HIDDEN / 64, MAXROWS / 128, 4), 256, SMEM>>>(b2, out, 4);

    // join side work
    cudaStreamWaitEvent(0, g_fj.evG2a, 0);
    cudaStreamWaitEvent(0, g_fj.evLoss, 0);
}

// round 15
// speedup vs baseline: 4.4568x; 1.0105x over previous
#include <cuda_runtime.h>
#include <cuda_bf16.h>
#include <math.h>

// Problem constants
#define NUM_EXPERTS 8
#define TOP_K 2
#define HIDDEN 512
#define INTER 2048
#define NTOK 2048
#define NSLOT (NTOK * TOP_K)
#define MAXROWS 2048

#define BKC 64            // k per chunk (128 B bf16 rows)
#define G_STAGE 49152     // per-stage smem: A hi/lo 32K + B hi/lo 16K

// ---------------- device scratch ----------------
__device__ int   g_cnt[NUM_EXPERTS];   // static zero-init; tail reset keeps invariant
__device__ int   g_tok[NUM_EXPERTS][MAXROWS];
__device__ float g_wt[NUM_EXPERTS][MAXROWS];
__device__ float g_probs[NTOK * NUM_EXPERTS];
__device__ __nv_bfloat16 g_xh[(size_t)NTOK * HIDDEN];
__device__ __nv_bfloat16 g_xl[(size_t)NTOK * HIDDEN];
__device__ __nv_bfloat16 g_hmid_hi[(size_t)NUM_EXPERTS * MAXROWS * INTER];
__device__ __nv_bfloat16 g_hmid_lo[(size_t)NUM_EXPERTS * MAXROWS * INTER];
__device__ __nv_bfloat16 g_w1t_hi[(size_t)NUM_EXPERTS * INTER * HIDDEN];
__device__ __nv_bfloat16 g_w1t_lo[(size_t)NUM_EXPERTS * INTER * HIDDEN];
__device__ __nv_bfloat16 g_w2t_hi[(size_t)NUM_EXPERTS * HIDDEN * INTER];
__device__ __nv_bfloat16 g_w2t_lo[(size_t)NUM_EXPERTS * HIDDEN * INTER];

// ---------------- host-side streams/events (static init, pre-checkpoint) ----
struct ForkJoin {
    cudaStream_t s1, s2;
    cudaEvent_t evRoot, evW1, evX, evW2M, evR, evLoss, evG1a, evG2a;
    ForkJoin() {
        cudaStreamCreateWithFlags(&s1, cudaStreamNonBlocking);
        cudaStreamCreateWithFlags(&s2, cudaStreamNonBlocking);
        cudaEventCreateWithFlags(&evRoot, cudaEventDisableTiming);
        cudaEventCreateWithFlags(&evW1, cudaEventDisableTiming);
        cudaEventCreateWithFlags(&evX, cudaEventDisableTiming);
        cudaEventCreateWithFlags(&evW2M, cudaEventDisableTiming);
        cudaEventCreateWithFlags(&evR, cudaEventDisableTiming);
        cudaEventCreateWithFlags(&evLoss, cudaEventDisableTiming);
        cudaEventCreateWithFlags(&evG1a, cudaEventDisableTiming);
        cudaEventCreateWithFlags(&evG2a, cudaEventDisableTiming);
    }
};
static ForkJoin g_fj;

// ---------------- helpers ----------------
__device__ __forceinline__ unsigned smem_u32(const void* p) {
    unsigned a;
    asm("{ .reg .u64 t; cvta.to.shared.u64 t, %1; cvt.u32.u64 %0, t; }"
        : "=r"(a) : "l"(p));
    return a;
}
__device__ __forceinline__ unsigned sw128(unsigned off) {
    return off ^ ((off >> 3) & 0x70);
}
__device__ __forceinline__ unsigned pack2_hi(float a, float b,
                                             __nv_bfloat16& ha, __nv_bfloat16& hb) {
    ha = __float2bfloat16(a);
    hb = __float2bfloat16(b);
    return (unsigned)__bfloat16_as_ushort(ha) | ((unsigned)__bfloat16_as_ushort(hb) << 16);
}
__device__ __forceinline__ float gelu_tanh(float x) {
    const float c = 0.7978845608028654f;
    float x3 = x * x * x;
    return 0.5f * x * (1.0f + tanhf(c * (x + 0.044715f * x3)));
}

#define CP16(dst, src, nbytes) \
    asm volatile("cp.async.cg.shared.global [%0], [%1], 16, %2;" \
        :: "r"(dst), "l"(src), "r"((unsigned)(nbytes)) : "memory")
#define CP_COMMIT() asm volatile("cp.async.commit_group;" ::: "memory")
#define CP_WAIT0()  asm volatile("cp.async.wait_group 0;" ::: "memory")

#define LDSM4(r, addr) \
    asm volatile("ldmatrix.sync.aligned.m8n8.x4.shared.b16 {%0,%1,%2,%3}, [%4];" \
        : "=r"((r)[0]), "=r"((r)[1]), "=r"((r)[2]), "=r"((r)[3]) : "r"(addr))

#define MMA16816(c, a, b0v, b1v) \
    asm volatile("mma.sync.aligned.m16n8k16.row.col.f32.bf16.bf16.f32 " \
        "{%0,%1,%2,%3}, {%4,%5,%6,%7}, {%8,%9}, {%0,%1,%2,%3};" \
        : "+f"((c)[0]), "+f"((c)[1]), "+f"((c)[2]), "+f"((c)[3]) \
        : "r"((a)[0]), "r"((a)[1]), "r"((a)[2]), "r"((a)[3]), "r"(b0v), "r"(b1v))

// ---------------- kernel: tail reset (runs LAST; static init covers run 1) ----
__global__ void reset_kernel() {
    int t = threadIdx.x;
    if (t < NUM_EXPERTS) g_cnt[t] = 0;
}

// ---------------- kernel: split activations (side stream) ----------------
__global__ void split_x_kernel(const float* __restrict__ hidden) {
    int i = blockIdx.x * 256 + threadIdx.x;  // one float4 per thread
    float4 v = *(const float4*)&hidden[(size_t)i * 4];
    __nv_bfloat16 h0, h1, h2, h3, d0, d1, d2, d3;
    unsigned hp0 = pack2_hi(v.x, v.y, h0, h1);
    unsigned hp1 = pack2_hi(v.z, v.w, h2, h3);
    unsigned lp0 = pack2_hi(v.x - __bfloat162float(h0), v.y - __bfloat162float(h1), d0, d1);
    unsigned lp1 = pack2_hi(v.z - __bfloat162float(h2), v.w - __bfloat162float(h3), d2, d3);
    *(uint2*)&g_xh[(size_t)i * 4] = make_uint2(hp0, hp1);
    *(uint2*)&g_xl[(size_t)i * 4] = make_uint2(lp0, lp1);
}

// ---------------- kernel 1: router ----------------
// 256 blocks x 256 threads; one warp per token; float4 dot products.
__global__ void __launch_bounds__(256)
router_kernel(const float* __restrict__ hidden,
              const float* __restrict__ w_router,
              const float* __restrict__ b_router) {
    __shared__ float wsm[NUM_EXPERTS][HIDDEN];
    int tid = threadIdx.x;
    for (int i = tid; i < NUM_EXPERTS * HIDDEN; i += 256) {
        int e = i / HIDDEN, h = i % HIDDEN;
        wsm[e][h] = w_router[h * NUM_EXPERTS + e];
    }
    __syncthreads();

    int warp = tid >> 5, lane = tid & 31;
    int t = blockIdx.x * 8 + warp;

    const float* x = hidden + (size_t)t * HIDDEN;
    float acc[NUM_EXPERTS];
#pragma unroll
    for (int e = 0; e < NUM_EXPERTS; e++) acc[e] = 0.f;
#pragma unroll
    for (int it = 0; it < HIDDEN / 128; it++) {
        int h = it * 128 + lane * 4;
        float4 v = *(const float4*)&x[h];
#pragma unroll
        for (int e = 0; e < NUM_EXPERTS; e++) {
            float4 w = *(const float4*)&wsm[e][h];
            acc[e] += v.x * w.x + v.y * w.y + v.z * w.z + v.w * w.w;
        }
    }
#pragma unroll
    for (int off = 16; off > 0; off >>= 1) {
#pragma unroll
        for (int e = 0; e < NUM_EXPERTS; e++)
            acc[e] += __shfl_xor_sync(0xffffffffu, acc[e], off);
    }
    if (lane == 0) {
        float logits[NUM_EXPERTS], mx = -1e30f;
#pragma unroll
        for (int e = 0; e < NUM_EXPERTS; e++) {
            logits[e] = acc[e] + b_router[e];
            mx = fmaxf(mx, logits[e]);
        }
        float p[NUM_EXPERTS], Z = 0.f;
#pragma unroll
        for (int e = 0; e < NUM_EXPERTS; e++) { p[e] = __expf(logits[e] - mx); Z += p[e]; }
        float invZ = 1.0f / Z;
#pragma unroll
        for (int e = 0; e < NUM_EXPERTS; e++) {
            p[e] *= invZ;
            g_probs[t * NUM_EXPERTS + e] = p[e];
        }
        int i1 = 0; float p1 = p[0];
#pragma unroll
        for (int e = 1; e < NUM_EXPERTS; e++) if (p[e] > p1) { p1 = p[e]; i1 = e; }
        int i2 = -1; float p2 = -1.0f;
#pragma unroll
        for (int e = 0; e < NUM_EXPERTS; e++)
            if (e != i1 && p[e] > p2) { p2 = p[e]; i2 = e; }
        float rs = 1.0f / (p1 + p2);
        int pos1 = atomicAdd(&g_cnt[i1], 1);
        g_tok[i1][pos1] = t; g_wt[i1][pos1] = p1 * rs;
        int pos2 = atomicAdd(&g_cnt[i2], 1);
        g_tok[i2][pos2] = t; g_wt[i2][pos2] = p2 * rs;
    }
}

// ---------------- kernel 2: balance loss (warp-per-expert) ----------------
__global__ void loss_kernel(float* __restrict__ out, int write_loss) {
    __shared__ float part[NUM_EXPERTS];
    int tid = threadIdx.x, wid = tid >> 5, lane = tid & 31;
    if (wid < NUM_EXPERTS) {
        float s = 0.f;
        for (int t = lane; t < NTOK; t += 32)
            s += g_probs[t * NUM_EXPERTS + wid];
#pragma unroll
        for (int off = 16; off > 0; off >>= 1)
            s += __shfl_xor_sync(0xffffffffu, s, off);
        if (lane == 0) part[wid] = s;
    }
    __syncthreads();
    if (tid == 0 && write_loss) {
        float acc = 0.f;
#pragma unroll
        for (int e = 0; e < NUM_EXPERTS; e++) {
            float P = part[e] / (float)NTOK;
            float f = (float)g_cnt[e] / (float)NSLOT;
            acc += f * P;
        }
        out[(size_t)NTOK * HIDDEN] = 0.01f * (float)NUM_EXPERTS * acc;
    }
}

// ---------------- kernel 3: transpose + split weights ----------------
__global__ void transpose_split_kernel(const float* __restrict__ w,
                                       int which, int K, int N) {
    __nv_bfloat16* hi = which ? g_w2t_hi : g_w1t_hi;
    __nv_bfloat16* lo = which ? g_w2t_lo : g_w1t_lo;
    __shared__ float tile[64][33];
    int e = blockIdx.z;
    int n0 = blockIdx.x * 32, k0 = blockIdx.y * 64;
    const float* we = w + (size_t)e * K * N;
    int tx = threadIdx.x, ty = threadIdx.y; // 32 x 8
#pragma unroll
    for (int r = 0; r < 8; r++) {
        int kl = ty + r * 8;
        tile[kl][tx] = we[(size_t)(k0 + kl) * N + n0 + tx];
    }
    __syncthreads();
#pragma unroll
    for (int r = 0; r < 4; r++) {
        int nl = ty + r * 8;
        float v0 = tile[2 * tx][nl];
        float v1 = tile[2 * tx + 1][nl];
        __nv_bfloat16 h0, h1, d0, d1;
        unsigned hp = pack2_hi(v0, v1, h0, h1);
        unsigned lp = pack2_hi(v0 - __bfloat162float(h0), v1 - __bfloat162float(h1), d0, d1);
        size_t o = ((size_t)e * N + n0 + nl) * K + k0 + 2 * tx;
        *(unsigned*)&hi[o] = hp;
        *(unsigned*)&lo[o] = lp;
    }
}

// ======================================================================
// GEMM1: hmid = gelu(gather(x) @ w1 + b1). CTA 128x64, cp.async 2-stage.
// 8 warps (2m x 4n), warp tile 64x16, 3-way bf16 split. 2 CTAs/SM.
// ======================================================================
__global__ void __launch_bounds__(256, 2)
gemm1_mma(const float* __restrict__ b1, int ebase) {
    int e = blockIdx.z + ebase;
    int cnt = g_cnt[e];
    int m0 = blockIdx.y * 128;
    if (m0 >= cnt) return;
    int n0 = blockIdx.x * 64;

    extern __shared__ char dsm[];
    unsigned sb = smem_u32(dsm);
    unsigned base = (sb + 1023u) & ~1023u;

    __shared__ int toks[128];
    int tid = threadIdx.x, wid = tid >> 5, lane = tid & 31;
    if (tid < 128) toks[tid] = (m0 + tid < cnt) ? g_tok[e][m0 + tid] : -1;
    __syncthreads();

    const __nv_bfloat16* w1h = g_w1t_hi + (size_t)e * INTER * HIDDEN;
    const __nv_bfloat16* w1l = g_w1t_lo + (size_t)e * INTER * HIDDEN;

    int wm = wid >> 2, wn = wid & 3;
    int rA = (lane & 7) + 8 * ((lane >> 3) & 1);
    int cA = lane >> 4;
    int rB = (lane & 7) + 8 * (lane >> 4);
    int cB = (lane >> 3) & 1;

    float acc[4][2][4];
#pragma unroll
    for (int i = 0; i < 4; i++)
#pragma unroll
        for (int j = 0; j < 2; j++)
#pragma unroll
            for (int q = 0; q < 4; q++) acc[i][j][q] = 0.f;

    const int KT = HIDDEN / BKC; // 8

    auto issue = [&](int kt, int s) {
        unsigned st = base + s * G_STAGE;
        int k0 = kt * BKC;
#pragma unroll
        for (int u = 0; u < 4; u++) {
            int idx = tid + u * 256;
            int row = idx >> 3, seg = idx & 7;
            unsigned so = sw128((unsigned)(row * 128 + seg * 16));
            int tok = toks[row];
            const __nv_bfloat16* sh = (tok >= 0) ? g_xh + (size_t)tok * HIDDEN + k0 + seg * 8 : g_xh;
            const __nv_bfloat16* sl = (tok >= 0) ? g_xl + (size_t)tok * HIDDEN + k0 + seg * 8 : g_xl;
            unsigned pb = (tok >= 0) ? 16u : 0u;
            CP16(st + so, sh, pb);
            CP16(st + 16384 + so, sl, pb);
        }
#pragma unroll
        for (int u = 0; u < 2; u++) {
            int idx = tid + u * 256;
            int row = idx >> 3, seg = idx & 7;
            unsigned so = sw128((unsigned)(row * 128 + seg * 16));
            size_t bsrc = (size_t)(n0 + row) * HIDDEN + k0 + seg * 8;
            CP16(st + 32768 + so, w1h + bsrc, 16u);
            CP16(st + 40960 + so, w1l + bsrc, 16u);
        }
        CP_COMMIT();
    };

    issue(0, 0);
    for (int kt = 0; kt < KT; kt++) {
        CP_WAIT0();
        __syncthreads();
        if (kt + 1 < KT) issue(kt + 1, (kt + 1) & 1);
        unsigned st = base + (kt & 1) * G_STAGE;
        unsigned uAh = st, uAl = st + 16384, uBh = st + 32768, uBl = st + 40960;
#pragma unroll
        for (int k16 = 0; k16 < 4; k16++) {
            unsigned Afh[4][4], Afl[4][4], Bfh[4], Bfl[4];
#pragma unroll
            for (int mt = 0; mt < 4; mt++) {
                unsigned off = sw128((unsigned)((64 * wm + 16 * mt + rA) * 128 + (2 * k16 + cA) * 16));
                LDSM4(Afh[mt], uAh + off);
                LDSM4(Afl[mt], uAl + off);
            }
            {
                unsigned off = sw128((unsigned)((16 * wn + rB) * 128 + (2 * k16 + cB) * 16));
                LDSM4(Bfh, uBh + off);
                LDSM4(Bfl, uBl + off);
            }
#pragma unroll
            for (int mt = 0; mt < 4; mt++)
#pragma unroll
                for (int nt = 0; nt < 2; nt++)
                    MMA16816(acc[mt][nt], Afh[mt], Bfh[nt * 2], Bfh[nt * 2 + 1]);
#pragma unroll
            for (int mt = 0; mt < 4; mt++)
#pragma unroll
                for (int nt = 0; nt < 2; nt++)
                    MMA16816(acc[mt][nt], Afl[mt], Bfh[nt * 2], Bfh[nt * 2 + 1]);
#pragma unroll
            for (int mt = 0; mt < 4; mt++)
#pragma unroll
                for (int nt = 0; nt < 2; nt++)
                    MMA16816(acc[mt][nt], Afh[mt], Bfl[nt * 2], Bfl[nt * 2 + 1]);
        }
        __syncthreads();
    }

    // epilogue: bias + gelu, split, write hmid hi/lo planes
    int g = lane >> 2, tg = lane & 3;
#pragma unroll
    for (int mt = 0; mt < 4; mt++) {
        int mA = m0 + 64 * wm + 16 * mt + g;
        int mB = mA + 8;
#pragma unroll
        for (int nt = 0; nt < 2; nt++) {
            int n = n0 + 16 * wn + 8 * nt + 2 * tg;
            float2 bb = *(const float2*)&b1[(size_t)e * INTER + n];
            if (mA < cnt) {
                float v0 = gelu_tanh(acc[mt][nt][0] + bb.x);
                float v1 = gelu_tanh(acc[mt][nt][1] + bb.y);
                __nv_bfloat16 h0, h1, d0, d1;
                unsigned hp = pack2_hi(v0, v1, h0, h1);
                unsigned lp = pack2_hi(v0 - __bfloat162float(h0), v1 - __bfloat162float(h1), d0, d1);
                size_t o = ((size_t)e * MAXROWS + mA) * INTER + n;
                *(unsigned*)&g_hmid_hi[o] = hp;
                *(unsigned*)&g_hmid_lo[o] = lp;
            }
            if (mB < cnt) {
                float v2 = gelu_tanh(acc[mt][nt][2] + bb.x);
                float v3 = gelu_tanh(acc[mt][nt][3] + bb.y);
                __nv_bfloat16 h2, h3, d2, d3;
                unsigned hp = pack2_hi(v2, v3, h2, h3);
                unsigned lp = pack2_hi(v2 - __bfloat162float(h2), v3 - __bfloat162float(h3), d2, d3);
                size_t o = ((size_t)e * MAXROWS + mB) * INTER + n;
                *(unsigned*)&g_hmid_hi[o] = hp;
                *(unsigned*)&g_hmid_lo[o] = lp;
            }
        }
    }
}

// ======================================================================
// GEMM2: out[tok] += wt*(hmid @ w2 + b2). CTA 128x64, cp.async 2-stage.
// ======================================================================
__global__ void __launch_bounds__(256, 2)
gemm2_mma(const float* __restrict__ b2, float* __restrict__ out, int ebase) {
    int e = blockIdx.z + ebase;
    int cnt = g_cnt[e];
    int m0 = blockIdx.y * 128;
    if (m0 >= cnt) return;
    int n0 = blockIdx.x * 64;

    extern __shared__ char dsm[];
    unsigned sb = smem_u32(dsm);
    unsigned base = (sb + 1023u) & ~1023u;

    int tid = threadIdx.x, wid = tid >> 5, lane = tid & 31;
    int wm = wid >> 2, wn = wid & 3;
    int rA = (lane & 7) + 8 * ((lane >> 3) & 1);
    int cA = lane >> 4;
    int rB = (lane & 7) + 8 * (lane >> 4);
    int cB = (lane >> 3) & 1;

    const __nv_bfloat16* w2h = g_w2t_hi + (size_t)e * HIDDEN * INTER;
    const __nv_bfloat16* w2l = g_w2t_lo + (size_t)e * HIDDEN * INTER;
    const __nv_bfloat16* ah = g_hmid_hi + (size_t)e * MAXROWS * INTER;
    const __nv_bfloat16* al = g_hmid_lo + (size_t)e * MAXROWS * INTER;

    float acc[4][2][4];
#pragma unroll
    for (int i = 0; i < 4; i++)
#pragma unroll
        for (int j = 0; j < 2; j++)
#pragma unroll
            for (int q = 0; q < 4; q++) acc[i][j][q] = 0.f;

    const int KT = INTER / BKC; // 32

    auto issue = [&](int kt, int s) {
        unsigned st = base + s * G_STAGE;
        int k0 = kt * BKC;
#pragma unroll
        for (int u = 0; u < 4; u++) {
            int idx = tid + u * 256;
            int row = idx >> 3, seg = idx & 7;
            unsigned so = sw128((unsigned)(row * 128 + seg * 16));
            int gm = m0 + row;
            size_t asrc = (size_t)gm * INTER + k0 + seg * 8;
            unsigned pb = (gm < cnt) ? 16u : 0u;
            const __nv_bfloat16* sh = (gm < cnt) ? ah + asrc : ah;
            const __nv_bfloat16* sl = (gm < cnt) ? al + asrc : al;
            CP16(st + so, sh, pb);
            CP16(st + 16384 + so, sl, pb);
        }
#pragma unroll
        for (int u = 0; u < 2; u++) {
            int idx = tid + u * 256;
            int row = idx >> 3, seg = idx & 7;
            unsigned so = sw128((unsigned)(row * 128 + seg * 16));
            size_t bsrc = (size_t)(n0 + row) * INTER + k0 + seg * 8;
            CP16(st + 32768 + so, w2h + bsrc, 16u);
            CP16(st + 40960 + so, w2l + bsrc, 16u);
        }
        CP_COMMIT();
    };

    issue(0, 0);
    for (int kt = 0; kt < KT; kt++) {
        CP_WAIT0();
        __syncthreads();
        if (kt + 1 < KT) issue(kt + 1, (kt + 1) & 1);
        unsigned st = base + (kt & 1) * G_STAGE;
        unsigned uAh = st, uAl = st + 16384, uBh = st + 32768, uBl = st + 40960;
#pragma unroll
        for (int k16 = 0; k16 < 4; k16++) {
            unsigned Afh[4][4], Afl[4][4], Bfh[4], Bfl[4];
#pragma unroll
            for (int mt = 0; mt < 4; mt++) {
                unsigned off = sw128((unsigned)((64 * wm + 16 * mt + rA) * 128 + (2 * k16 + cA) * 16));
                LDSM4(Afh[mt], uAh + off);
                LDSM4(Afl[mt], uAl + off);
            }
            {
                unsigned off = sw128((unsigned)((16 * wn + rB) * 128 + (2 * k16 + cB) * 16));
                LDSM4(Bfh, uBh + off);
                LDSM4(Bfl, uBl + off);
            }
#pragma unroll
            for (int mt = 0; mt < 4; mt++)
#pragma unroll
                for (int nt = 0; nt < 2; nt++)
                    MMA16816(acc[mt][nt], Afh[mt], Bfh[nt * 2], Bfh[nt * 2 + 1]);
#pragma unroll
            for (int mt = 0; mt < 4; mt++)
#pragma unroll
                for (int nt = 0; nt < 2; nt++)
                    MMA16816(acc[mt][nt], Afl[mt], Bfh[nt * 2], Bfh[nt * 2 + 1]);
#pragma unroll
            for (int mt = 0; mt < 4; mt++)
#pragma unroll
                for (int nt = 0; nt < 2; nt++)
                    MMA16816(acc[mt][nt], Afh[mt], Bfl[nt * 2], Bfl[nt * 2 + 1]);
        }
        __syncthreads();
    }

    // epilogue: weighted atomic accumulate onto residual out
    int g = lane >> 2, tg = lane & 3;
#pragma unroll
    for (int mt = 0; mt < 4; mt++) {
        int mA = m0 + 64 * wm + 16 * mt + g;
        int mB = mA + 8;
        float wA = (mA < cnt) ? g_wt[e][mA] : 0.f;
        float wB = (mB < cnt) ? g_wt[e][mB] : 0.f;
        int tokA = (mA < cnt) ? g_tok[e][mA] : 0;
        int tokB = (mB < cnt) ? g_tok[e][mB] : 0;
#pragma unroll
        for (int nt = 0; nt < 2; nt++) {
            int n = n0 + 16 * wn + 8 * nt + 2 * tg;
            float2 bb = *(const float2*)&b2[(size_t)e * HIDDEN + n];
            if (mA < cnt) {
                float* op = out + (size_t)tokA * HIDDEN + n;
                atomicAdd(op,     (acc[mt][nt][0] + bb.x) * wA);
                atomicAdd(op + 1, (acc[mt][nt][1] + bb.y) * wA);
            }
            if (mB < cnt) {
                float* op = out + (size_t)tokB * HIDDEN + n;
                atomicAdd(op,     (acc[mt][nt][2] + bb.x) * wB);
                atomicAdd(op + 1, (acc[mt][nt][3] + bb.y) * wB);
            }
        }
    }
}

// ---------------- launch ----------------
extern "C" void kernel_launch(void* const* d_in, const int* in_sizes, int n_in,
                              void* d_out, int out_size) {
    const float* hidden   = (const float*)d_in[0];
    const float* w_router = (const float*)d_in[1];
    const float* b_router = (const float*)d_in[2];
    const float* w1       = (const float*)d_in[3];
    const float* b1       = (const float*)d_in[4];
    const float* w2       = (const float*)d_in[5];
    const float* b2       = (const float*)d_in[6];
    float* out = (float*)d_out;

    const int SMEM = 2 * G_STAGE + 1024;  // 99328
    cudaFuncSetAttribute(gemm1_mma, cudaFuncAttributeMaxDynamicSharedMemorySize, SMEM);
    cudaFuncSetAttribute(gemm2_mma, cudaFuncAttributeMaxDynamicSharedMemorySize, SMEM);

    // ---- fork ----
    cudaEventRecord(g_fj.evRoot, 0);
    cudaStreamWaitEvent(g_fj.s1, g_fj.evRoot, 0);
    cudaStreamWaitEvent(g_fj.s2, g_fj.evRoot, 0);

    // s1: w1 transpose only (shortest gate for gemm1)
    transpose_split_kernel<<<dim3(INTER / 32, HIDDEN / 64, NUM_EXPERTS), dim3(32, 8), 0, g_fj.s1>>>(
        w1, 0, HIDDEN, INTER);
    cudaEventRecord(g_fj.evW1, g_fj.s1);

    // s2: split_x first (gemm1 gate), then w2 transpose + residual memcpy
    split_x_kernel<<<NTOK * HIDDEN / 1024, 256, 0, g_fj.s2>>>(hidden);
    cudaEventRecord(g_fj.evX, g_fj.s2);
    transpose_split_kernel<<<dim3(HIDDEN / 32, INTER / 64, NUM_EXPERTS), dim3(32, 8), 0, g_fj.s2>>>(
        w2, 1, INTER, HIDDEN);
    cudaMemcpyAsync(out, hidden, (size_t)NTOK * HIDDEN * sizeof(float),
                    cudaMemcpyDeviceToDevice, g_fj.s2);
    cudaEventRecord(g_fj.evW2M, g_fj.s2);

    // main: router immediately (g_cnt is zero by static-init / tail reset)
    router_kernel<<<NTOK / 8, 256>>>(hidden, w_router, b_router);
    cudaEventRecord(g_fj.evR, 0);

    // loss on s1 (after router); overlaps with gemms
    cudaStreamWaitEvent(g_fj.s1, g_fj.evR, 0);
    int write_loss = (out_size > NTOK * HIDDEN) ? 1 : 0;
    loss_kernel<<<1, 256, 0, g_fj.s1>>>(out, write_loss);
    cudaEventRecord(g_fj.evLoss, g_fj.s1);

    // main: gemm1a (experts 0-3) after w1t + split_x
    cudaStreamWaitEvent(0, g_fj.evW1, 0);
    cudaStreamWaitEvent(0, g_fj.evX, 0);
    gemm1_mma<<<dim3(INTER / 64, MAXROWS / 128, 4), 256, SMEM>>>(b1, 0);
    cudaEventRecord(g_fj.evG1a, 0);
    // main: gemm1b (experts 4-7)
    gemm1_mma<<<dim3(INTER / 64, MAXROWS / 128, 4), 256, SMEM>>>(b1, 4);

    // s2: gemm2a (experts 0-3) after gemm1a (+ w2t/memcpy implicit on s2)
    cudaStreamWaitEvent(g_fj.s2, g_fj.evG1a, 0);
    gemm2_mma<<<dim3(HIDDEN / 64, MAXROWS / 128, 4), 256, SMEM, g_fj.s2>>>(b2, out, 0);
    cudaEventRecord(g_fj.evG2a, g_fj.s2);

    // main: gemm2b (experts 4-7) after gemm1b (implicit) + w2t/memcpy
    cudaStreamWaitEvent(0, g_fj.evW2M, 0);
    gemm2_mma<<<dim3(HIDDEN / 64, MAXROWS / 128, 4), 256, SMEM>>>(b2, out, 4);

    // join side work, then tail reset restores g_cnt=0 for the next replay
    cudaStreamWaitEvent(0, g_fj.evG2a, 0);
    cudaStreamWaitEvent(0, g_fj.evLoss, 0);
    reset_kernel<<<1, 32>>>();
}